// round 15
// baseline (speedup 1.0000x reference)
#include <cuda_runtime.h>
#include <cuda_bf16.h>
#include <math_constants.h>
#include <cstdint>

// Problem shape (fixed by the dataset)
#define TB 8
#define TT 2048
#define TC 1024
#define TM_TOTAL (TB*TT)      // 16384 rows

// ===================== scratch (no allocations allowed) =====================
__device__ float g_buf0[TB * TC * TT];          // q_t [B,C,T] -> attn_t
__device__ float g_buf1[TB * TC * TT];          // k_t [B,C,T] -> (y1 + h2 + bias) [B,T,C]
__device__ float g_vsum[TB * TT];
__device__ float g_wvs [TC + 1];
__device__ float2 g_tw [1024];                  // e^{-2pi i j/2048}

// tf32 operands, chunk-tiled fp32: [kc=32][row][32] (128B rows, SW128)
__device__ float g_xt [TM_TOTAL * TC];
__device__ float g_y1t[TM_TOTAL * TC];
__device__ float g_h1t[TM_TOTAL * TC];
__device__ float g_w32[4 * TC * TC];

// ===================== PTX helpers =====================
__device__ __forceinline__ uint32_t smem_u32(const void* p) {
    uint32_t a;
    asm("{ .reg .u64 t; cvta.to.shared.u64 t, %1; cvt.u32.u64 %0, t; }" : "=r"(a) : "l"(p));
    return a;
}
#define SMEM_SWIZZLE_128B(o) ((o) ^ (((o) >> 3) & 0x70))

#define MBARRIER_INIT(mb, cnt) \
    asm volatile("mbarrier.init.shared.b64 [%0], %1;" :: "r"((uint32_t)(mb)), "r"((uint32_t)(cnt)) : "memory")
#define MBARRIER_EXPECT_TX(mb, bytes) \
    asm volatile("mbarrier.arrive.expect_tx.shared.b64 _, [%0], %1;" :: "r"((uint32_t)(mb)), "r"((uint32_t)(bytes)) : "memory")
#define MBARRIER_WAIT_PARITY(mb, ph) do { \
    uint32_t _m = (uint32_t)(mb); uint32_t _p = (uint32_t)(ph); uint32_t _d; \
    asm volatile("{\n\t.reg .pred p;\n\tmbarrier.try_wait.parity.acquire.cta.shared::cta.b64 p, [%1], %2;\n\tselp.b32 %0, 1, 0, p;\n\t}" \
        : "=r"(_d) : "r"(_m), "r"(_p) : "memory"); \
    if (!_d) { \
        asm volatile("{\n\t.reg .pred P1;\n\tWL_%=:\n\tmbarrier.try_wait.parity.acquire.cta.shared::cta.b64 P1, [%0], %1, 0x989680;\n\t@P1 bra.uni WD_%=;\n\tbra.uni WL_%=;\n\tWD_%=:\n\t}" \
            :: "r"(_m), "r"(_p) : "memory"); \
    } } while (0)

#define BULK_G2S(dst, src, bytes, mbar) \
    asm volatile("cp.async.bulk.shared::cluster.global.mbarrier::complete_tx::bytes [%0], [%1], %2, [%3];" \
        :: "r"((uint32_t)(dst)), "l"(src), "r"((uint32_t)(bytes)), "r"((uint32_t)(mbar)) : "memory")

__device__ __forceinline__ void ldsm_x4(uint32_t* r, uint32_t addr) {
    asm volatile("ldmatrix.sync.aligned.m8n8.x4.shared.b16 {%0,%1,%2,%3}, [%4];"
                 : "=r"(r[0]), "=r"(r[1]), "=r"(r[2]), "=r"(r[3]) : "r"(addr));
}
__device__ __forceinline__ void ldsm_x2(uint32_t* r, uint32_t addr) {
    asm volatile("ldmatrix.sync.aligned.m8n8.x2.shared.b16 {%0,%1}, [%2];"
                 : "=r"(r[0]), "=r"(r[1]) : "r"(addr));
}
__device__ __forceinline__ void mma_tf32(float* d, const uint32_t* a, const uint32_t* b) {
    asm volatile("mma.sync.aligned.m16n8k8.row.col.f32.tf32.tf32.f32 "
                 "{%0,%1,%2,%3}, {%4,%5,%6,%7}, {%8,%9}, {%0,%1,%2,%3};"
                 : "+f"(d[0]), "+f"(d[1]), "+f"(d[2]), "+f"(d[3])
                 : "r"(a[0]), "r"(a[1]), "r"(a[2]), "r"(a[3]), "r"(b[0]), "r"(b[1]));
}
__device__ __forceinline__ float tf32r(float x) {
    uint32_t o;
    asm("cvt.rna.tf32.f32 %0, %1;" : "=r"(o) : "f"(x));
    return __uint_as_float(o);
}

// element index of (row r, col k) in fp32 chunked array (32 fp32/row) with R rows
__device__ __forceinline__ size_t chunk32_pos(int r, int k, int R) {
    uint32_t inb = SMEM_SWIZZLE_128B((uint32_t)((r & 127) * 128 + (k & 31) * 4));
    return (size_t)(k >> 5) * ((size_t)R * 32) + (size_t)(r & ~127) * 32 + (inb >> 2);
}

// ===================== block reductions (256 threads) =====================
__device__ __forceinline__ float blk_reduce_sum(float v, float* sbuf) {
    #pragma unroll
    for (int o = 16; o; o >>= 1) v += __shfl_xor_sync(0xffffffffu, v, o);
    if ((threadIdx.x & 31) == 0) sbuf[threadIdx.x >> 5] = v;
    __syncthreads();
    if (threadIdx.x < 32) {
        float w = (threadIdx.x < 8) ? sbuf[threadIdx.x] : 0.0f;
        #pragma unroll
        for (int o = 4; o; o >>= 1) w += __shfl_xor_sync(0xffffffffu, w, o);
        if (threadIdx.x == 0) sbuf[0] = w;
    }
    __syncthreads();
    float r = sbuf[0];
    __syncthreads();
    return r;
}
__device__ __forceinline__ float blk_reduce_max(float v, float* sbuf) {
    #pragma unroll
    for (int o = 16; o; o >>= 1) v = fmaxf(v, __shfl_xor_sync(0xffffffffu, v, o));
    if ((threadIdx.x & 31) == 0) sbuf[threadIdx.x >> 5] = v;
    __syncthreads();
    if (threadIdx.x < 32) {
        float w = (threadIdx.x < 8) ? sbuf[threadIdx.x] : -CUDART_INF_F;
        #pragma unroll
        for (int o = 4; o; o >>= 1) w = fmaxf(w, __shfl_xor_sync(0xffffffffu, w, o));
        if (threadIdx.x == 0) sbuf[0] = w;
    }
    __syncthreads();
    float r = sbuf[0];
    __syncthreads();
    return r;
}
__device__ __forceinline__ float2 blk_reduce_sum2(float a, float b, float* sbuf) {
    #pragma unroll
    for (int o = 16; o; o >>= 1) {
        a += __shfl_xor_sync(0xffffffffu, a, o);
        b += __shfl_xor_sync(0xffffffffu, b, o);
    }
    if ((threadIdx.x & 31) == 0) {
        sbuf[threadIdx.x >> 5] = a;
        sbuf[8 + (threadIdx.x >> 5)] = b;
    }
    __syncthreads();
    if (threadIdx.x < 32) {
        float wa = (threadIdx.x < 8) ? sbuf[threadIdx.x] : 0.0f;
        float wb = (threadIdx.x < 8) ? sbuf[8 + threadIdx.x] : 0.0f;
        #pragma unroll
        for (int o = 4; o; o >>= 1) {
            wa += __shfl_xor_sync(0xffffffffu, wa, o);
            wb += __shfl_xor_sync(0xffffffffu, wb, o);
        }
        if (threadIdx.x == 0) { sbuf[0] = wa; sbuf[1] = wb; }
    }
    __syncthreads();
    float2 r = make_float2(sbuf[0], sbuf[1]);
    __syncthreads();
    return r;
}

// ===================== tf32 single-pass GEMM (round-13 champion mainloop) =====================
// D[16384,1024] = A @ Wt^T + bias; A/Wt tf32-rounded fp32 in chunk32 layout.
// EPI: 0 = fp32 [M,N] + bias;  1 = fp32 transposed [B,C,T] + bias;
//      2 = relu + tf32 chunk32;  3 = fp32 [M,N] + bias + y1t residual (pre-LN2 sum)
#define BM 128
#define BN 128
#define NCH32 32
#define TSZ32 16384                     // 128 rows x 128B
#define ST32 (2*TSZ32)                  // 32KB
#define NST32 4
#define MB32_OFF (NST32*ST32)
#define GEMM32_SMEM (NST32*ST32 + 64)

__device__ __forceinline__ void gemm32_issue(const char* pA, const char* pB,
                                             int kc, uint32_t dst, uint32_t mb)
{
    MBARRIER_EXPECT_TX(mb, ST32);
    BULK_G2S(dst,         pA + (size_t)kc * ((size_t)TM_TOTAL * 128), TSZ32, mb);
    BULK_G2S(dst + TSZ32, pB + (size_t)kc * ((size_t)TC * 128),       TSZ32, mb);
}

template<int EPI>
__global__ void __launch_bounds__(256, 1)
gemm_tf32k(const float* __restrict__ A, const float* __restrict__ B,
           const float* __restrict__ bias, float* out_f, float* out_t)
{
    extern __shared__ char smem[];
    const uint32_t sb = smem_u32(smem);
    const int tid = threadIdx.x;
    const int wid = tid >> 5;
    const int lane = tid & 31;
    const int wm = wid & 1;
    const int wn = wid >> 1;
    const int n0 = blockIdx.x * BN;
    const int m0 = blockIdx.y * BM;

    const char* pA = (const char*)A + (size_t)m0 * 128;
    const char* pB = (const char*)B + (size_t)n0 * 128;

    if (tid == 0) {
        #pragma unroll
        for (int s = 0; s < NST32; s++) MBARRIER_INIT(sb + MB32_OFF + 8*s, 1);
    }
    __syncthreads();
    if (tid == 0) {
        #pragma unroll
        for (int s = 0; s < NST32; s++)
            gemm32_issue(pA, pB, s, sb + s*ST32, sb + MB32_OFF + 8*s);
    }

    float acc[4][4][4];
    #pragma unroll
    for (int mi = 0; mi < 4; mi++)
        #pragma unroll
        for (int ni = 0; ni < 4; ni++)
            #pragma unroll
            for (int e = 0; e < 4; e++) acc[mi][ni][e] = 0.0f;

    int ph[NST32] = {0, 0, 0, 0};
    int s = 0;
    #pragma unroll 1
    for (int kc = 0; kc < NCH32; kc++) {
        MBARRIER_WAIT_PARITY(sb + MB32_OFF + 8*s, ph[s]); ph[s] ^= 1;
        const uint32_t st = sb + s * ST32;
        #pragma unroll
        for (int ks = 0; ks < 4; ks++) {
            uint32_t af[4][4], bfr[4][2];
            // A frag (m16k8 tf32)
            const int arow = wm * 64 + ((lane >> 3) & 1) * 8 + (lane & 7);
            const int acolb = ks * 32 + (lane >> 4) * 16;
            #pragma unroll
            for (int mi = 0; mi < 4; mi++) {
                uint32_t o = SMEM_SWIZZLE_128B((uint32_t)((arow + mi*16) * 128 + acolb));
                ldsm_x4(af[mi], st + o);
            }
            // B frag (k8n8 tf32)
            const int brow = wn * 32 + (lane & 7);
            const int bcolb = ks * 32 + ((lane >> 3) & 1) * 16;
            #pragma unroll
            for (int ni = 0; ni < 4; ni++) {
                uint32_t o = SMEM_SWIZZLE_128B((uint32_t)((brow + ni*8) * 128 + bcolb));
                ldsm_x2(bfr[ni], st + TSZ32 + o);
            }
            #pragma unroll
            for (int mi = 0; mi < 4; mi++)
                #pragma unroll
                for (int ni = 0; ni < 4; ni++)
                    mma_tf32(acc[mi][ni], af[mi], bfr[ni]);
        }
        __syncthreads();
        if (kc + NST32 < NCH32 && tid == 0)
            gemm32_issue(pA, pB, kc + NST32, st, sb + MB32_OFF + 8*s);
        s = (s == NST32-1) ? 0 : s + 1;
    }

    float* stile = (float*)smem;
    {
        const int rg = lane >> 2;
        const int cg = (lane & 3) * 2;
        #pragma unroll
        for (int mi = 0; mi < 4; mi++)
            #pragma unroll
            for (int ni = 0; ni < 4; ni++) {
                int r = wm*64 + mi*16 + rg;
                int c = wn*32 + ni*8 + cg;
                stile[r*133 + c]         = acc[mi][ni][0];
                stile[r*133 + c + 1]     = acc[mi][ni][1];
                stile[(r+8)*133 + c]     = acc[mi][ni][2];
                stile[(r+8)*133 + c + 1] = acc[mi][ni][3];
            }
    }
    __syncthreads();

    if (EPI == 0) {
        for (int idx = tid; idx < BM*BN; idx += 256) {
            int r = idx >> 7, c = idx & 127;
            out_f[(size_t)(m0 + r) * TC + n0 + c] = stile[r*133 + c] + __ldg(bias + n0 + c);
        }
    } else if (EPI == 1) {
        const int b = m0 >> 11, t0 = m0 & (TT - 1);
        for (int idx = tid; idx < BM*BN; idx += 256) {
            int n = idx >> 7, cm = idx & 127;
            float v = stile[cm*133 + n] + __ldg(bias + n0 + n);
            out_f[((size_t)(b * TC + n0 + n)) * TT + t0 + cm] = v;
        }
    } else if (EPI == 2) {
        for (int idx = tid; idx < BM*BN; idx += 256) {
            int r = idx >> 7, c = idx & 127;
            float v = fmaxf(stile[r*133 + c] + __ldg(bias + n0 + c), 0.0f);
            out_t[chunk32_pos(m0 + r, n0 + c, TM_TOTAL)] = tf32r(v);
        }
    } else {
        // EPI 3: h2 + bias + y1 residual (out_t = y1t input)
        for (int idx = tid; idx < BM*BN; idx += 256) {
            int r = idx >> 7, c = idx & 127;
            float v = stile[r*133 + c] + __ldg(bias + n0 + c)
                    + out_t[chunk32_pos(m0 + r, n0 + c, TM_TOTAL)];
            out_f[(size_t)(m0 + r) * TC + n0 + c] = v;
        }
    }
}

// ===================== fused: fp32 x -> tf32 chunk32 + vsum GEMV =====================
__global__ void __launch_bounds__(256)
split_vsum_kernel(const float* __restrict__ x, const float* __restrict__ wvs,
                  float* __restrict__ xt, float* __restrict__ vsum)
{
    __shared__ float sbuf[32];
    const int m = blockIdx.x;
    const int tid = threadIdx.x;
    const float* xr = x + (size_t)m * TC;

    const int c = tid * 4;
    float4 v = *(const float4*)(xr + c);
    float s = v.x * __ldg(wvs + c) + v.y * __ldg(wvs + c + 1)
            + v.z * __ldg(wvs + c + 2) + v.w * __ldg(wvs + c + 3);

    float4 t;
    t.x = tf32r(v.x); t.y = tf32r(v.y); t.z = tf32r(v.z); t.w = tf32r(v.w);
    *(float4*)(xt + chunk32_pos(m, c, TM_TOTAL)) = t;

    s = blk_reduce_sum(s, sbuf);
    if (tid == 0) vsum[m] = s + __ldg(wvs + TC);
}

// ===================== W[K,N] -> Wt[N,K] tf32 chunk32 =====================
__global__ void transpose_w32(const float* __restrict__ W, float* __restrict__ out)
{
    __shared__ float tile[32][33];
    const int n0 = blockIdx.x * 32;
    const int k0 = blockIdx.y * 32;
    #pragma unroll
    for (int y = threadIdx.y; y < 32; y += 8)
        tile[y][threadIdx.x] = W[(size_t)(k0 + y) * TC + n0 + threadIdx.x];
    __syncthreads();
    #pragma unroll
    for (int y = threadIdx.y; y < 32; y += 8)
        out[chunk32_pos(n0 + y, k0 + threadIdx.x, TC)] = tf32r(tile[threadIdx.x][y]);
}

// ===================== wvsum / twiddles =====================
__global__ void wvsum_kernel(const float* __restrict__ Wv, const float* __restrict__ bv,
                             float* __restrict__ out)
{
    __shared__ float sbuf[32];
    int d = blockIdx.x;
    const float* src = (d < TC) ? (Wv + (size_t)d * TC) : bv;
    float s = 0.0f;
    for (int c = threadIdx.x; c < TC; c += 256) s += src[c];
    s = blk_reduce_sum(s, sbuf);
    if (threadIdx.x == 0) out[d] = s;
}
__global__ void init_tw_kernel(float2* __restrict__ tw)
{
    int j = blockIdx.x * 256 + threadIdx.x;
    float sv, cv;
    sincosf(-6.283185307179586f * ((float)j * (1.0f / 2048.0f)), &sv, &cv);
    tw[j] = make_float2(cv, sv);
}

// ===================== FFT machinery =====================
__device__ __forceinline__ float2 cmulf(float2 a, float2 b) {
    return make_float2(a.x*b.x - a.y*b.y, a.x*b.y + a.y*b.x);
}
#define BFLY(u, v, w) do { \
    float2 _t = cmulf(v, w); \
    v = make_float2(u.x - _t.x, u.y - _t.y); \
    u = make_float2(u.x + _t.x, u.y + _t.y); \
} while (0)

template<int H>
__device__ __forceinline__ void fft_r4_pass(float2* z, const float2* tw, int tid, bool inv)
{
    #pragma unroll
    for (int jj = 0; jj < 2; jj++) {
        int j = tid + jj * 256;
        int grp = j / H;
        int p = j & (H - 1);
        int i0 = grp * 4 * H + p;
        float2 w1 = tw[p * (1024 / H)];
        float2 w2 = tw[p * (512 / H)];
        if (inv) { w1.y = -w1.y; w2.y = -w2.y; }
        float2 w2b = inv ? make_float2(-w2.y, w2.x) : make_float2(w2.y, -w2.x);
        float2 e0 = z[i0], e1 = z[i0+H], e2 = z[i0+2*H], e3 = z[i0+3*H];
        BFLY(e0, e1, w1);
        BFLY(e2, e3, w1);
        BFLY(e0, e2, w2);
        BFLY(e1, e3, w2b);
        z[i0] = e0; z[i0+H] = e1; z[i0+2*H] = e2; z[i0+3*H] = e3;
    }
}

template<int H>
__device__ __forceinline__ void fft_r8_pass(float2* z, const float2* tw, int tid, bool inv)
{
    const int g = tid / H;
    const int p = tid % H;
    const int i0 = g * 8 * H + p;
    float2 w1 = tw[p * (1024 / H)];
    float2 w2 = tw[p * (512 / H)];
    float2 w3 = tw[p * (256 / H)];
    if (inv) { w1.y = -w1.y; w2.y = -w2.y; w3.y = -w3.y; }
    const float R = 0.70710678118654752440f;
    const float2 c8 = inv ? make_float2(R, R) : make_float2(R, -R);
    float2 w2b  = inv ? make_float2(-w2.y, w2.x)   : make_float2(w2.y, -w2.x);
    float2 w3_1 = cmulf(w3, c8);
    float2 w3_2 = inv ? make_float2(-w3.y, w3.x)   : make_float2(w3.y, -w3.x);
    float2 w3_3 = inv ? make_float2(-w3_1.y, w3_1.x) : make_float2(w3_1.y, -w3_1.x);

    float2 e0 = z[i0],       e1 = z[i0+H],   e2 = z[i0+2*H], e3 = z[i0+3*H];
    float2 e4 = z[i0+4*H],   e5 = z[i0+5*H], e6 = z[i0+6*H], e7 = z[i0+7*H];
    BFLY(e0, e1, w1); BFLY(e2, e3, w1); BFLY(e4, e5, w1); BFLY(e6, e7, w1);
    BFLY(e0, e2, w2); BFLY(e1, e3, w2b); BFLY(e4, e6, w2); BFLY(e5, e7, w2b);
    BFLY(e0, e4, w3); BFLY(e1, e5, w3_1); BFLY(e2, e6, w3_2); BFLY(e3, e7, w3_3);
    z[i0] = e0;       z[i0+H] = e1;   z[i0+2*H] = e2; z[i0+3*H] = e3;
    z[i0+4*H] = e4;   z[i0+5*H] = e5; z[i0+6*H] = e6; z[i0+7*H] = e7;
}

template<bool DUAL>
__device__ __forceinline__ void fft_seq(float2* za, float2* zb, const float2* tw, int tid, bool inv)
{
    fft_r4_pass<1>(za, tw, tid, inv);
    if (DUAL) fft_r4_pass<1>(zb, tw, tid, inv);
    __syncthreads();
    fft_r8_pass<4>(za, tw, tid, inv);
    if (DUAL) fft_r8_pass<4>(zb, tw, tid, inv);
    __syncthreads();
    fft_r8_pass<32>(za, tw, tid, inv);
    if (DUAL) fft_r8_pass<32>(zb, tw, tid, inv);
    __syncthreads();
    fft_r8_pass<256>(za, tw, tid, inv);
    if (DUAL) fft_r8_pass<256>(zb, tw, tid, inv);
    __syncthreads();
}

__global__ void __launch_bounds__(256)
fft_corr_softmax(const float* qt, const float* kt,
                 const float* __restrict__ vsum, const float2* __restrict__ gtw,
                 float* attn_t)
{
    __shared__ float2 zq[2048];
    __shared__ float2 zk[2048];
    __shared__ float2 tw[1024];
    __shared__ float sbuf[32];

    const int pc = blockIdx.x;
    const int b = pc >> 9;
    const int c0 = (pc & 511) * 2;
    const int tid = threadIdx.x;
    const float* q0 = qt + ((size_t)b * TC + c0) * TT;
    const float* q1 = q0 + TT;
    const float* k0 = kt + ((size_t)b * TC + c0) * TT;
    const float* k1 = k0 + TT;

    #pragma unroll
    for (int i = 0; i < 2; i++) {
        int j = tid + i * 256;
        ((float4*)tw)[j] = __ldg((const float4*)gtw + j);
    }
    #pragma unroll
    for (int i = 0; i < 8; i++) {
        int t = tid + i * 256;
        int r = __brev((unsigned)t) >> 21;
        zq[r] = make_float2(q0[t], q1[t]);
        zk[r] = make_float2(k0[t], k1[t]);
    }
    __syncthreads();

    fft_seq<true>(zq, zk, tw, tid, false);

    for (int f = tid; f <= 1024; f += 256) {
        int g = (2048 - f) & 2047;
        float2 aq = zq[f], bq = zq[g];
        float2 ak = zk[f], bk = zk[g];
        float Q0r = 0.5f*(aq.x + bq.x), Q0i = 0.5f*(aq.y - bq.y);
        float Q1r = 0.5f*(aq.y + bq.y), Q1i = 0.5f*(bq.x - aq.x);
        float K0r = 0.5f*(ak.x + bk.x), K0i = 0.5f*(ak.y - bk.y);
        float K1r = 0.5f*(ak.y + bk.y), K1i = 0.5f*(bk.x - ak.x);
        float P0r = Q0r*K0r + Q0i*K0i, P0i = Q0i*K0r - Q0r*K0i;
        float P1r = Q1r*K1r + Q1i*K1i, P1i = Q1i*K1r - Q1r*K1i;
        zq[f] = make_float2(P0r - P1i, P0i + P1r);
        zq[g] = make_float2(P0r + P1i, P1r - P0i);
    }
    __syncthreads();

    #pragma unroll
    for (int i = 0; i < 8; i++) {
        int t = tid + i * 256;
        int r = __brev((unsigned)t) >> 21;
        if (r > t) { float2 a = zq[t]; zq[t] = zq[r]; zq[r] = a; }
    }
    __syncthreads();
    fft_seq<false>(zq, nullptr, tw, tid, true);

    float c0v[8], c1v[8];
    float m0 = -CUDART_INF_F, m1 = -CUDART_INF_F;
    #pragma unroll
    for (int i = 0; i < 8; i++) {
        int t = tid + i * 256;
        float2 w = zq[t];
        c0v[i] = w.x * (1.0f / 2048.0f);
        c1v[i] = w.y * (1.0f / 2048.0f);
        m0 = fmaxf(m0, c0v[i]);
        m1 = fmaxf(m1, c1v[i]);
    }
    m0 = blk_reduce_max(m0, sbuf);
    m1 = blk_reduce_max(m1, sbuf);
    float s0 = 0.0f, s1 = 0.0f;
    #pragma unroll
    for (int i = 0; i < 8; i++) {
        c0v[i] = expf(c0v[i] - m0);
        c1v[i] = expf(c1v[i] - m1);
        s0 += c0v[i];
        s1 += c1v[i];
    }
    s0 = blk_reduce_sum(s0, sbuf);
    s1 = blk_reduce_sum(s1, sbuf);
    float i0 = 1.0f / s0, i1 = 1.0f / s1;

    const float* vs = vsum + (size_t)b * TT;
    float* a0 = attn_t + ((size_t)b * TC + c0) * TT;
    float* a1 = a0 + TT;
    #pragma unroll
    for (int i = 0; i < 8; i++) {
        int t = tid + i * 256;
        float v = vs[t];
        a0[t] = c0v[i] * i0 * v;
        a1[t] = c1v[i] * i1 * v;
    }
}

// ===================== fused: transpose + residual + LN1 -> tf32 chunk32 =====================
#define TROWS 8
#define TPAD 1025
#define LN1_SMEM (TROWS * TPAD * 4)

__global__ void __launch_bounds__(256)
trans_add_ln8(const float* __restrict__ attn_t, const float* __restrict__ x,
              const float* __restrict__ g, const float* __restrict__ be,
              float* __restrict__ y1t)
{
    extern __shared__ float s[];
    __shared__ float sbuf[64];
    const int b  = blockIdx.y;
    const int t0 = blockIdx.x * TROWS;
    const int tid = threadIdx.x;

    #pragma unroll
    for (int i = 0; i < 32; i++) {
        int idx = tid + i * 256;
        int c = idx >> 3, j = idx & 7;
        s[j * TPAD + c] = attn_t[((size_t)b * TC + c) * TT + t0 + j];
    }
    __syncthreads();
    #pragma unroll
    for (int i = 0; i < 32; i++) {
        int idx = tid + i * 256;
        int j = idx >> 10, c = idx & 1023;
        s[j * TPAD + c] += x[((size_t)b * TT + t0 + j) * TC + c];
    }
    __syncthreads();

    #pragma unroll 1
    for (int j = 0; j < TROWS; j++) {
        const int row = b * TT + t0 + j;
        const float* srow = s + j * TPAD;
        float a = 0.0f, q = 0.0f;
        float v[4];
        #pragma unroll
        for (int i = 0; i < 4; i++) {
            v[i] = srow[i * 256 + tid];
            a += v[i];
            q += v[i] * v[i];
        }
        float2 r = blk_reduce_sum2(a, q, sbuf);
        float mean = r.x * (1.0f / (float)TC);
        float var  = r.y * (1.0f / (float)TC) - mean * mean;
        float rstd = rsqrtf(var + 1e-5f);
        #pragma unroll
        for (int i = 0; i < 4; i++) {
            int c = i * 256 + tid;
            float y = (v[i] - mean) * rstd * __ldg(g + c) + __ldg(be + c);
            y1t[chunk32_pos(row, c, TM_TOTAL)] = tf32r(y);
        }
    }
}

// ===================== LN2 on pre-summed input -> final out =====================
__global__ void __launch_bounds__(256)
ln2_kernel(const float* __restrict__ v_in,
           const float* __restrict__ g, const float* __restrict__ be,
           float* __restrict__ out)
{
    __shared__ float sbuf[64];
    int row = blockIdx.x;
    const float* vr = v_in + (size_t)row * TC;
    int tid = threadIdx.x;

    float v[4];
    float a = 0.0f, q = 0.0f;
    #pragma unroll
    for (int i = 0; i < 4; i++) {
        int c = i * 256 + tid;
        v[i] = vr[c];
        a += v[i];
        q += v[i] * v[i];
    }
    float2 r = blk_reduce_sum2(a, q, sbuf);
    float mean = r.x * (1.0f / (float)TC);
    float var  = r.y * (1.0f / (float)TC) - mean * mean;
    float rstd = rsqrtf(var + 1e-5f);
    #pragma unroll
    for (int i = 0; i < 4; i++) {
        int c = i * 256 + tid;
        out[(size_t)row * TC + c] = (v[i] - mean) * rstd * g[c] + be[c];
    }
}

// ===================== launcher =====================
extern "C" void kernel_launch(void* const* d_in, const int* in_sizes, int n_in,
                              void* d_out, int out_size)
{
    const float* x   = (const float*)d_in[0];
    const float* Wq  = (const float*)d_in[1];
    const float* bq  = (const float*)d_in[2];
    const float* Wk  = (const float*)d_in[3];
    const float* bk  = (const float*)d_in[4];
    const float* Wv  = (const float*)d_in[5];
    const float* bv  = (const float*)d_in[6];
    const float* g1  = (const float*)d_in[7];
    const float* be1 = (const float*)d_in[8];
    const float* W1  = (const float*)d_in[9];
    const float* bf1 = (const float*)d_in[10];
    const float* W2  = (const float*)d_in[11];
    const float* bf2 = (const float*)d_in[12];
    const float* g2  = (const float*)d_in[13];
    const float* be2 = (const float*)d_in[14];

    float *buf0, *buf1, *vsum, *wvs, *xt, *y1t, *h1t, *w32;
    float2* tw;
    cudaGetSymbolAddress((void**)&buf0, g_buf0);
    cudaGetSymbolAddress((void**)&buf1, g_buf1);
    cudaGetSymbolAddress((void**)&vsum, g_vsum);
    cudaGetSymbolAddress((void**)&wvs,  g_wvs);
    cudaGetSymbolAddress((void**)&tw,   g_tw);
    cudaGetSymbolAddress((void**)&xt,   g_xt);
    cudaGetSymbolAddress((void**)&y1t,  g_y1t);
    cudaGetSymbolAddress((void**)&h1t,  g_h1t);
    cudaGetSymbolAddress((void**)&w32,  g_w32);

    cudaFuncSetAttribute(gemm_tf32k<0>, cudaFuncAttributeMaxDynamicSharedMemorySize, GEMM32_SMEM);
    cudaFuncSetAttribute(gemm_tf32k<1>, cudaFuncAttributeMaxDynamicSharedMemorySize, GEMM32_SMEM);
    cudaFuncSetAttribute(gemm_tf32k<2>, cudaFuncAttributeMaxDynamicSharedMemorySize, GEMM32_SMEM);
    cudaFuncSetAttribute(gemm_tf32k<3>, cudaFuncAttributeMaxDynamicSharedMemorySize, GEMM32_SMEM);
    cudaFuncSetAttribute(trans_add_ln8, cudaFuncAttributeMaxDynamicSharedMemorySize, LN1_SMEM);

    const int M = TM_TOTAL;
    const size_t WSTRIDE = (size_t)TC * TC;
    dim3 wgrid(32, 32), wblk(32, 8);
    dim3 ggrid(TC / BN, M / BM);   // (8, 128)

    // prep (q-GEMM kept as 5th launch for ncu -s 5 -c 1)
    transpose_w32<<<wgrid, wblk>>>(Wq, w32 + 0*WSTRIDE);                          // 1
    transpose_w32<<<wgrid, wblk>>>(Wk, w32 + 1*WSTRIDE);                          // 2
    wvsum_kernel<<<TC + 1, 256>>>(Wv, bv, wvs);                                   // 3
    split_vsum_kernel<<<M, 256>>>(x, wvs, xt, vsum);                              // 4

    // q_t, k_t in [B,C,T] via tf32 GEMM with transposed epilogue
    gemm_tf32k<1><<<ggrid, 256, GEMM32_SMEM>>>(xt, w32 + 0*WSTRIDE, bq, buf0, nullptr);  // 5
    gemm_tf32k<1><<<ggrid, 256, GEMM32_SMEM>>>(xt, w32 + 1*WSTRIDE, bk, buf1, nullptr);  // 6

    // remaining prep
    init_tw_kernel<<<4, 256>>>(tw);
    transpose_w32<<<wgrid, wblk>>>(W1, w32 + 2*WSTRIDE);
    transpose_w32<<<wgrid, wblk>>>(W2, w32 + 3*WSTRIDE);

    // FFT xcorr + softmax + *vsum (channel-paired, radix-8 passes)
    fft_corr_softmax<<<TB * TC / 2, 256>>>(buf0, buf1, vsum, tw, buf0);

    // fused transpose + residual + LN1 -> tf32 chunk32
    trans_add_ln8<<<dim3(TT / TROWS, TB), 256, LN1_SMEM>>>(buf0, x, g1, be1, y1t);

    // FFN: tf32 GEMMs; h2 epilogue fuses the +y1 residual (pre-LN2 sum into buf1)
    gemm_tf32k<2><<<ggrid, 256, GEMM32_SMEM>>>(y1t, w32 + 2*WSTRIDE, bf1, nullptr, h1t);
    gemm_tf32k<3><<<ggrid, 256, GEMM32_SMEM>>>(h1t, w32 + 3*WSTRIDE, bf2, buf1, y1t);

    // LN2 on pre-summed input -> out
    ln2_kernel<<<M, 256>>>(buf1, g2, be2, (float*)d_out);
}

// round 16
// speedup vs baseline: 1.1656x; 1.1656x over previous
#include <cuda_runtime.h>
#include <cuda_bf16.h>
#include <math_constants.h>
#include <cstdint>

// Problem shape (fixed by the dataset)
#define TB 8
#define TT 2048
#define TC 1024
#define TM_TOTAL (TB*TT)      // 16384 rows

// ===================== scratch (no allocations allowed) =====================
__device__ float g_buf0[TB * TC * TT];          // q_t [B,C,T] -> attn_t
__device__ float g_buf1[TB * TC * TT];          // k_t [B,C,T] -> h2 [B,T,C]
__device__ float g_vsum[TB * TT];
__device__ float g_wvs [TC + 1];
__device__ float2 g_tw [1024];                  // e^{-2pi i j/2048}

// tf32 operands, chunk-tiled fp32: [kc=32][row][32] (128B rows, SW128)
__device__ float g_xt [TM_TOTAL * TC];
__device__ float g_y1t[TM_TOTAL * TC];
__device__ float g_h1t[TM_TOTAL * TC];
__device__ float g_w32[4 * TC * TC];

// ===================== PTX helpers =====================
__device__ __forceinline__ uint32_t smem_u32(const void* p) {
    uint32_t a;
    asm("{ .reg .u64 t; cvta.to.shared.u64 t, %1; cvt.u32.u64 %0, t; }" : "=r"(a) : "l"(p));
    return a;
}
#define SMEM_SWIZZLE_128B(o) ((o) ^ (((o) >> 3) & 0x70))

#define MBARRIER_INIT(mb, cnt) \
    asm volatile("mbarrier.init.shared.b64 [%0], %1;" :: "r"((uint32_t)(mb)), "r"((uint32_t)(cnt)) : "memory")
#define MBARRIER_EXPECT_TX(mb, bytes) \
    asm volatile("mbarrier.arrive.expect_tx.shared.b64 _, [%0], %1;" :: "r"((uint32_t)(mb)), "r"((uint32_t)(bytes)) : "memory")
#define MBARRIER_WAIT_PARITY(mb, ph) do { \
    uint32_t _m = (uint32_t)(mb); uint32_t _p = (uint32_t)(ph); uint32_t _d; \
    asm volatile("{\n\t.reg .pred p;\n\tmbarrier.try_wait.parity.acquire.cta.shared::cta.b64 p, [%1], %2;\n\tselp.b32 %0, 1, 0, p;\n\t}" \
        : "=r"(_d) : "r"(_m), "r"(_p) : "memory"); \
    if (!_d) { \
        asm volatile("{\n\t.reg .pred P1;\n\tWL_%=:\n\tmbarrier.try_wait.parity.acquire.cta.shared::cta.b64 P1, [%0], %1, 0x989680;\n\t@P1 bra.uni WD_%=;\n\tbra.uni WL_%=;\n\tWD_%=:\n\t}" \
            :: "r"(_m), "r"(_p) : "memory"); \
    } } while (0)

#define BULK_G2S(dst, src, bytes, mbar) \
    asm volatile("cp.async.bulk.shared::cluster.global.mbarrier::complete_tx::bytes [%0], [%1], %2, [%3];" \
        :: "r"((uint32_t)(dst)), "l"(src), "r"((uint32_t)(bytes)), "r"((uint32_t)(mbar)) : "memory")

__device__ __forceinline__ void ldsm_x4(uint32_t* r, uint32_t addr) {
    asm volatile("ldmatrix.sync.aligned.m8n8.x4.shared.b16 {%0,%1,%2,%3}, [%4];"
                 : "=r"(r[0]), "=r"(r[1]), "=r"(r[2]), "=r"(r[3]) : "r"(addr));
}
__device__ __forceinline__ void ldsm_x2(uint32_t* r, uint32_t addr) {
    asm volatile("ldmatrix.sync.aligned.m8n8.x2.shared.b16 {%0,%1}, [%2];"
                 : "=r"(r[0]), "=r"(r[1]) : "r"(addr));
}
__device__ __forceinline__ void mma_tf32(float* d, const uint32_t* a, const uint32_t* b) {
    asm volatile("mma.sync.aligned.m16n8k8.row.col.f32.tf32.tf32.f32 "
                 "{%0,%1,%2,%3}, {%4,%5,%6,%7}, {%8,%9}, {%0,%1,%2,%3};"
                 : "+f"(d[0]), "+f"(d[1]), "+f"(d[2]), "+f"(d[3])
                 : "r"(a[0]), "r"(a[1]), "r"(a[2]), "r"(a[3]), "r"(b[0]), "r"(b[1]));
}
__device__ __forceinline__ float tf32r(float x) {
    uint32_t o;
    asm("cvt.rna.tf32.f32 %0, %1;" : "=r"(o) : "f"(x));
    return __uint_as_float(o);
}

// element index of (row r, col k) in fp32 chunked array (32 fp32/row) with R rows
__device__ __forceinline__ size_t chunk32_pos(int r, int k, int R) {
    uint32_t inb = SMEM_SWIZZLE_128B((uint32_t)((r & 127) * 128 + (k & 31) * 4));
    return (size_t)(k >> 5) * ((size_t)R * 32) + (size_t)(r & ~127) * 32 + (inb >> 2);
}

// ===================== block reductions (256 threads) =====================
__device__ __forceinline__ float blk_reduce_sum(float v, float* sbuf) {
    #pragma unroll
    for (int o = 16; o; o >>= 1) v += __shfl_xor_sync(0xffffffffu, v, o);
    if ((threadIdx.x & 31) == 0) sbuf[threadIdx.x >> 5] = v;
    __syncthreads();
    if (threadIdx.x < 32) {
        float w = (threadIdx.x < 8) ? sbuf[threadIdx.x] : 0.0f;
        #pragma unroll
        for (int o = 4; o; o >>= 1) w += __shfl_xor_sync(0xffffffffu, w, o);
        if (threadIdx.x == 0) sbuf[0] = w;
    }
    __syncthreads();
    float r = sbuf[0];
    __syncthreads();
    return r;
}
__device__ __forceinline__ float blk_reduce_max(float v, float* sbuf) {
    #pragma unroll
    for (int o = 16; o; o >>= 1) v = fmaxf(v, __shfl_xor_sync(0xffffffffu, v, o));
    if ((threadIdx.x & 31) == 0) sbuf[threadIdx.x >> 5] = v;
    __syncthreads();
    if (threadIdx.x < 32) {
        float w = (threadIdx.x < 8) ? sbuf[threadIdx.x] : -CUDART_INF_F;
        #pragma unroll
        for (int o = 4; o; o >>= 1) w = fmaxf(w, __shfl_xor_sync(0xffffffffu, w, o));
        if (threadIdx.x == 0) sbuf[0] = w;
    }
    __syncthreads();
    float r = sbuf[0];
    __syncthreads();
    return r;
}
__device__ __forceinline__ float2 blk_reduce_sum2(float a, float b, float* sbuf) {
    #pragma unroll
    for (int o = 16; o; o >>= 1) {
        a += __shfl_xor_sync(0xffffffffu, a, o);
        b += __shfl_xor_sync(0xffffffffu, b, o);
    }
    if ((threadIdx.x & 31) == 0) {
        sbuf[threadIdx.x >> 5] = a;
        sbuf[8 + (threadIdx.x >> 5)] = b;
    }
    __syncthreads();
    if (threadIdx.x < 32) {
        float wa = (threadIdx.x < 8) ? sbuf[threadIdx.x] : 0.0f;
        float wb = (threadIdx.x < 8) ? sbuf[8 + threadIdx.x] : 0.0f;
        #pragma unroll
        for (int o = 4; o; o >>= 1) {
            wa += __shfl_xor_sync(0xffffffffu, wa, o);
            wb += __shfl_xor_sync(0xffffffffu, wb, o);
        }
        if (threadIdx.x == 0) { sbuf[0] = wa; sbuf[1] = wb; }
    }
    __syncthreads();
    float2 r = make_float2(sbuf[0], sbuf[1]);
    __syncthreads();
    return r;
}

// ===================== tf32 single-pass GEMM =====================
// D[16384,1024] = A @ Wt^T + bias; A/Wt tf32-rounded fp32 in chunk32 layout.
// EPI: 0 = fp32 [M,N] + bias;  1 = fp32 transposed [B,C,T] + bias;  2 = relu + tf32 chunk32
#define BM 128
#define BN 128
#define NCH32 32
#define TSZ32 16384                     // 128 rows x 128B
#define ST32 (2*TSZ32)                  // 32KB
#define NST32 4
#define MB32_OFF (NST32*ST32)
#define GEMM32_SMEM (NST32*ST32 + 64)

__device__ __forceinline__ void gemm32_issue(const char* pA, const char* pB,
                                             int kc, uint32_t dst, uint32_t mb)
{
    MBARRIER_EXPECT_TX(mb, ST32);
    BULK_G2S(dst,         pA + (size_t)kc * ((size_t)TM_TOTAL * 128), TSZ32, mb);
    BULK_G2S(dst + TSZ32, pB + (size_t)kc * ((size_t)TC * 128),       TSZ32, mb);
}

template<int EPI>
__global__ void __launch_bounds__(256, 1)
gemm_tf32k(const float* __restrict__ A, const float* __restrict__ B,
           const float* __restrict__ bias, float* out_f, float* out_t)
{
    extern __shared__ char smem[];
    const uint32_t sb = smem_u32(smem);
    const int tid = threadIdx.x;
    const int wid = tid >> 5;
    const int lane = tid & 31;
    const int wm = wid & 1;
    const int wn = wid >> 1;
    const int n0 = blockIdx.x * BN;
    const int m0 = blockIdx.y * BM;

    const char* pA = (const char*)A + (size_t)m0 * 128;
    const char* pB = (const char*)B + (size_t)n0 * 128;

    if (tid == 0) {
        #pragma unroll
        for (int s = 0; s < NST32; s++) MBARRIER_INIT(sb + MB32_OFF + 8*s, 1);
    }
    __syncthreads();
    if (tid == 0) {
        #pragma unroll
        for (int s = 0; s < NST32; s++)
            gemm32_issue(pA, pB, s, sb + s*ST32, sb + MB32_OFF + 8*s);
    }

    float acc[4][4][4];
    #pragma unroll
    for (int mi = 0; mi < 4; mi++)
        #pragma unroll
        for (int ni = 0; ni < 4; ni++)
            #pragma unroll
            for (int e = 0; e < 4; e++) acc[mi][ni][e] = 0.0f;

    int ph[NST32] = {0, 0, 0, 0};
    int s = 0;
    #pragma unroll 1
    for (int kc = 0; kc < NCH32; kc++) {
        MBARRIER_WAIT_PARITY(sb + MB32_OFF + 8*s, ph[s]); ph[s] ^= 1;
        const uint32_t st = sb + s * ST32;
        #pragma unroll
        for (int ks = 0; ks < 4; ks++) {
            uint32_t af[4][4], bfr[4][2];
            // A frag (m16k8 tf32): lanes 0-7 mat0 (r,k0..3), 8-15 mat1 (r+8), 16-23 mat2 (k+4), 24-31 mat3
            const int arow = wm * 64 + ((lane >> 3) & 1) * 8 + (lane & 7);
            const int acolb = ks * 32 + (lane >> 4) * 16;
            #pragma unroll
            for (int mi = 0; mi < 4; mi++) {
                uint32_t o = SMEM_SWIZZLE_128B((uint32_t)((arow + mi*16) * 128 + acolb));
                ldsm_x4(af[mi], st + o);
            }
            // B frag (k8n8 tf32): lanes 0-7 mat0 (n,k0..3), 8-15 mat1 (k+4)
            const int brow = wn * 32 + (lane & 7);
            const int bcolb = ks * 32 + ((lane >> 3) & 1) * 16;
            #pragma unroll
            for (int ni = 0; ni < 4; ni++) {
                uint32_t o = SMEM_SWIZZLE_128B((uint32_t)((brow + ni*8) * 128 + bcolb));
                ldsm_x2(bfr[ni], st + TSZ32 + o);
            }
            #pragma unroll
            for (int mi = 0; mi < 4; mi++)
                #pragma unroll
                for (int ni = 0; ni < 4; ni++)
                    mma_tf32(acc[mi][ni], af[mi], bfr[ni]);
        }
        __syncthreads();
        if (kc + NST32 < NCH32 && tid == 0)
            gemm32_issue(pA, pB, kc + NST32, st, sb + MB32_OFF + 8*s);
        s = (s == NST32-1) ? 0 : s + 1;
    }

    float* stile = (float*)smem;
    {
        const int rg = lane >> 2;
        const int cg = (lane & 3) * 2;
        #pragma unroll
        for (int mi = 0; mi < 4; mi++)
            #pragma unroll
            for (int ni = 0; ni < 4; ni++) {
                int r = wm*64 + mi*16 + rg;
                int c = wn*32 + ni*8 + cg;
                stile[r*133 + c]         = acc[mi][ni][0];
                stile[r*133 + c + 1]     = acc[mi][ni][1];
                stile[(r+8)*133 + c]     = acc[mi][ni][2];
                stile[(r+8)*133 + c + 1] = acc[mi][ni][3];
            }
    }
    __syncthreads();

    if (EPI == 0) {
        for (int idx = tid; idx < BM*BN; idx += 256) {
            int r = idx >> 7, c = idx & 127;
            out_f[(size_t)(m0 + r) * TC + n0 + c] = stile[r*133 + c] + __ldg(bias + n0 + c);
        }
    } else if (EPI == 1) {
        const int b = m0 >> 11, t0 = m0 & (TT - 1);
        for (int idx = tid; idx < BM*BN; idx += 256) {
            int n = idx >> 7, cm = idx & 127;
            float v = stile[cm*133 + n] + __ldg(bias + n0 + n);
            out_f[((size_t)(b * TC + n0 + n)) * TT + t0 + cm] = v;
        }
    } else {
        for (int idx = tid; idx < BM*BN; idx += 256) {
            int r = idx >> 7, c = idx & 127;
            float v = fmaxf(stile[r*133 + c] + __ldg(bias + n0 + c), 0.0f);
            out_t[chunk32_pos(m0 + r, n0 + c, TM_TOTAL)] = tf32r(v);
        }
    }
}

// ===================== fused: fp32 x -> tf32 chunk32 + vsum GEMV =====================
__global__ void __launch_bounds__(256)
split_vsum_kernel(const float* __restrict__ x, const float* __restrict__ wvs,
                  float* __restrict__ xt, float* __restrict__ vsum)
{
    __shared__ float sbuf[32];
    const int m = blockIdx.x;
    const int tid = threadIdx.x;
    const float* xr = x + (size_t)m * TC;

    const int c = tid * 4;
    float4 v = *(const float4*)(xr + c);
    float s = v.x * __ldg(wvs + c) + v.y * __ldg(wvs + c + 1)
            + v.z * __ldg(wvs + c + 2) + v.w * __ldg(wvs + c + 3);

    float4 t;
    t.x = tf32r(v.x); t.y = tf32r(v.y); t.z = tf32r(v.z); t.w = tf32r(v.w);
    *(float4*)(xt + chunk32_pos(m, c, TM_TOTAL)) = t;

    s = blk_reduce_sum(s, sbuf);
    if (tid == 0) vsum[m] = s + __ldg(wvs + TC);
}

// ===================== W[K,N] -> Wt[N,K] tf32 chunk32 =====================
__global__ void transpose_w32(const float* __restrict__ W, float* __restrict__ out)
{
    __shared__ float tile[32][33];
    const int n0 = blockIdx.x * 32;
    const int k0 = blockIdx.y * 32;
    #pragma unroll
    for (int y = threadIdx.y; y < 32; y += 8)
        tile[y][threadIdx.x] = W[(size_t)(k0 + y) * TC + n0 + threadIdx.x];
    __syncthreads();
    #pragma unroll
    for (int y = threadIdx.y; y < 32; y += 8)
        out[chunk32_pos(n0 + y, k0 + threadIdx.x, TC)] = tf32r(tile[threadIdx.x][y]);
}

// ===================== wvsum / twiddles =====================
__global__ void wvsum_kernel(const float* __restrict__ Wv, const float* __restrict__ bv,
                             float* __restrict__ out)
{
    __shared__ float sbuf[32];
    int d = blockIdx.x;
    const float* src = (d < TC) ? (Wv + (size_t)d * TC) : bv;
    float s = 0.0f;
    for (int c = threadIdx.x; c < TC; c += 256) s += src[c];
    s = blk_reduce_sum(s, sbuf);
    if (threadIdx.x == 0) out[d] = s;
}
__global__ void init_tw_kernel(float2* __restrict__ tw)
{
    int j = blockIdx.x * 256 + threadIdx.x;
    float sv, cv;
    sincosf(-6.283185307179586f * ((float)j * (1.0f / 2048.0f)), &sv, &cv);
    tw[j] = make_float2(cv, sv);
}

// ===================== FFT machinery =====================
__device__ __forceinline__ float2 cmulf(float2 a, float2 b) {
    return make_float2(a.x*b.x - a.y*b.y, a.x*b.y + a.y*b.x);
}
#define BFLY(u, v, w) do { \
    float2 _t = cmulf(v, w); \
    v = make_float2(u.x - _t.x, u.y - _t.y); \
    u = make_float2(u.x + _t.x, u.y + _t.y); \
} while (0)

template<int H>
__device__ __forceinline__ void fft_r4_pass(float2* z, const float2* tw, int tid, bool inv)
{
    #pragma unroll
    for (int jj = 0; jj < 2; jj++) {
        int j = tid + jj * 256;
        int grp = j / H;
        int p = j & (H - 1);
        int i0 = grp * 4 * H + p;
        float2 w1 = tw[p * (1024 / H)];
        float2 w2 = tw[p * (512 / H)];
        if (inv) { w1.y = -w1.y; w2.y = -w2.y; }
        float2 w2b = inv ? make_float2(-w2.y, w2.x) : make_float2(w2.y, -w2.x);
        float2 e0 = z[i0], e1 = z[i0+H], e2 = z[i0+2*H], e3 = z[i0+3*H];
        BFLY(e0, e1, w1);
        BFLY(e2, e3, w1);
        BFLY(e0, e2, w2);
        BFLY(e1, e3, w2b);
        z[i0] = e0; z[i0+H] = e1; z[i0+2*H] = e2; z[i0+3*H] = e3;
    }
}

template<int H>
__device__ __forceinline__ void fft_r8_pass(float2* z, const float2* tw, int tid, bool inv)
{
    const int g = tid / H;
    const int p = tid % H;
    const int i0 = g * 8 * H + p;
    float2 w1 = tw[p * (1024 / H)];
    float2 w2 = tw[p * (512 / H)];
    float2 w3 = tw[p * (256 / H)];
    if (inv) { w1.y = -w1.y; w2.y = -w2.y; w3.y = -w3.y; }
    const float R = 0.70710678118654752440f;
    const float2 c8 = inv ? make_float2(R, R) : make_float2(R, -R);
    float2 w2b  = inv ? make_float2(-w2.y, w2.x)   : make_float2(w2.y, -w2.x);
    float2 w3_1 = cmulf(w3, c8);
    float2 w3_2 = inv ? make_float2(-w3.y, w3.x)   : make_float2(w3.y, -w3.x);
    float2 w3_3 = inv ? make_float2(-w3_1.y, w3_1.x) : make_float2(w3_1.y, -w3_1.x);

    float2 e0 = z[i0],       e1 = z[i0+H],   e2 = z[i0+2*H], e3 = z[i0+3*H];
    float2 e4 = z[i0+4*H],   e5 = z[i0+5*H], e6 = z[i0+6*H], e7 = z[i0+7*H];
    BFLY(e0, e1, w1); BFLY(e2, e3, w1); BFLY(e4, e5, w1); BFLY(e6, e7, w1);
    BFLY(e0, e2, w2); BFLY(e1, e3, w2b); BFLY(e4, e6, w2); BFLY(e5, e7, w2b);
    BFLY(e0, e4, w3); BFLY(e1, e5, w3_1); BFLY(e2, e6, w3_2); BFLY(e3, e7, w3_3);
    z[i0] = e0;       z[i0+H] = e1;   z[i0+2*H] = e2; z[i0+3*H] = e3;
    z[i0+4*H] = e4;   z[i0+5*H] = e5; z[i0+6*H] = e6; z[i0+7*H] = e7;
}

template<bool DUAL>
__device__ __forceinline__ void fft_seq(float2* za, float2* zb, const float2* tw, int tid, bool inv)
{
    fft_r4_pass<1>(za, tw, tid, inv);
    if (DUAL) fft_r4_pass<1>(zb, tw, tid, inv);
    __syncthreads();
    fft_r8_pass<4>(za, tw, tid, inv);
    if (DUAL) fft_r8_pass<4>(zb, tw, tid, inv);
    __syncthreads();
    fft_r8_pass<32>(za, tw, tid, inv);
    if (DUAL) fft_r8_pass<32>(zb, tw, tid, inv);
    __syncthreads();
    fft_r8_pass<256>(za, tw, tid, inv);
    if (DUAL) fft_r8_pass<256>(zb, tw, tid, inv);
    __syncthreads();
}

__global__ void __launch_bounds__(256)
fft_corr_softmax(const float* qt, const float* kt,
                 const float* __restrict__ vsum, const float2* __restrict__ gtw,
                 float* attn_t)
{
    __shared__ float2 zq[2048];
    __shared__ float2 zk[2048];
    __shared__ float2 tw[1024];
    __shared__ float sbuf[32];

    const int pc = blockIdx.x;
    const int b = pc >> 9;
    const int c0 = (pc & 511) * 2;
    const int tid = threadIdx.x;
    const float* q0 = qt + ((size_t)b * TC + c0) * TT;
    const float* q1 = q0 + TT;
    const float* k0 = kt + ((size_t)b * TC + c0) * TT;
    const float* k1 = k0 + TT;

    #pragma unroll
    for (int i = 0; i < 2; i++) {
        int j = tid + i * 256;
        ((float4*)tw)[j] = __ldg((const float4*)gtw + j);
    }
    #pragma unroll
    for (int i = 0; i < 8; i++) {
        int t = tid + i * 256;
        int r = __brev((unsigned)t) >> 21;
        zq[r] = make_float2(q0[t], q1[t]);
        zk[r] = make_float2(k0[t], k1[t]);
    }
    __syncthreads();

    fft_seq<true>(zq, zk, tw, tid, false);

    for (int f = tid; f <= 1024; f += 256) {
        int g = (2048 - f) & 2047;
        float2 aq = zq[f], bq = zq[g];
        float2 ak = zk[f], bk = zk[g];
        float Q0r = 0.5f*(aq.x + bq.x), Q0i = 0.5f*(aq.y - bq.y);
        float Q1r = 0.5f*(aq.y + bq.y), Q1i = 0.5f*(bq.x - aq.x);
        float K0r = 0.5f*(ak.x + bk.x), K0i = 0.5f*(ak.y - bk.y);
        float K1r = 0.5f*(ak.y + bk.y), K1i = 0.5f*(bk.x - ak.x);
        float P0r = Q0r*K0r + Q0i*K0i, P0i = Q0i*K0r - Q0r*K0i;
        float P1r = Q1r*K1r + Q1i*K1i, P1i = Q1i*K1r - Q1r*K1i;
        zq[f] = make_float2(P0r - P1i, P0i + P1r);
        zq[g] = make_float2(P0r + P1i, P1r - P0i);
    }
    __syncthreads();

    #pragma unroll
    for (int i = 0; i < 8; i++) {
        int t = tid + i * 256;
        int r = __brev((unsigned)t) >> 21;
        if (r > t) { float2 a = zq[t]; zq[t] = zq[r]; zq[r] = a; }
    }
    __syncthreads();
    fft_seq<false>(zq, nullptr, tw, tid, true);

    float c0v[8], c1v[8];
    float m0 = -CUDART_INF_F, m1 = -CUDART_INF_F;
    #pragma unroll
    for (int i = 0; i < 8; i++) {
        int t = tid + i * 256;
        float2 w = zq[t];
        c0v[i] = w.x * (1.0f / 2048.0f);
        c1v[i] = w.y * (1.0f / 2048.0f);
        m0 = fmaxf(m0, c0v[i]);
        m1 = fmaxf(m1, c1v[i]);
    }
    m0 = blk_reduce_max(m0, sbuf);
    m1 = blk_reduce_max(m1, sbuf);
    float s0 = 0.0f, s1 = 0.0f;
    #pragma unroll
    for (int i = 0; i < 8; i++) {
        c0v[i] = expf(c0v[i] - m0);
        c1v[i] = expf(c1v[i] - m1);
        s0 += c0v[i];
        s1 += c1v[i];
    }
    s0 = blk_reduce_sum(s0, sbuf);
    s1 = blk_reduce_sum(s1, sbuf);
    float i0 = 1.0f / s0, i1 = 1.0f / s1;

    const float* vs = vsum + (size_t)b * TT;
    float* a0 = attn_t + ((size_t)b * TC + c0) * TT;
    float* a1 = a0 + TT;
    #pragma unroll
    for (int i = 0; i < 8; i++) {
        int t = tid + i * 256;
        float v = vs[t];
        a0[t] = c0v[i] * i0 * v;
        a1[t] = c1v[i] * i1 * v;
    }
}

// ===================== fused: transpose + residual + LN1 -> tf32 chunk32 =====================
#define TROWS 8
#define TPAD 1025
#define LN1_SMEM (TROWS * TPAD * 4)

__global__ void __launch_bounds__(256)
trans_add_ln8(const float* __restrict__ attn_t, const float* __restrict__ x,
              const float* __restrict__ g, const float* __restrict__ be,
              float* __restrict__ y1t)
{
    extern __shared__ float s[];
    __shared__ float sbuf[64];
    const int b  = blockIdx.y;
    const int t0 = blockIdx.x * TROWS;
    const int tid = threadIdx.x;

    #pragma unroll
    for (int i = 0; i < 32; i++) {
        int idx = tid + i * 256;
        int c = idx >> 3, j = idx & 7;
        s[j * TPAD + c] = attn_t[((size_t)b * TC + c) * TT + t0 + j];
    }
    __syncthreads();
    #pragma unroll
    for (int i = 0; i < 32; i++) {
        int idx = tid + i * 256;
        int j = idx >> 10, c = idx & 1023;
        s[j * TPAD + c] += x[((size_t)b * TT + t0 + j) * TC + c];
    }
    __syncthreads();

    #pragma unroll 1
    for (int j = 0; j < TROWS; j++) {
        const int row = b * TT + t0 + j;
        const float* srow = s + j * TPAD;
        float a = 0.0f, q = 0.0f;
        float v[4];
        #pragma unroll
        for (int i = 0; i < 4; i++) {
            v[i] = srow[i * 256 + tid];
            a += v[i];
            q += v[i] * v[i];
        }
        float2 r = blk_reduce_sum2(a, q, sbuf);
        float mean = r.x * (1.0f / (float)TC);
        float var  = r.y * (1.0f / (float)TC) - mean * mean;
        float rstd = rsqrtf(var + 1e-5f);
        #pragma unroll
        for (int i = 0; i < 4; i++) {
            int c = i * 256 + tid;
            float y = (v[i] - mean) * rstd * __ldg(g + c) + __ldg(be + c);
            y1t[chunk32_pos(row, c, TM_TOTAL)] = tf32r(y);
        }
    }
}

// ===================== LN2: residual from y1t + h2 fp32 -> final out =====================
__global__ void __launch_bounds__(256)
ln2_kernel(const float* __restrict__ h2, const float* __restrict__ y1t,
           const float* __restrict__ g, const float* __restrict__ be,
           float* __restrict__ out)
{
    __shared__ float sbuf[64];
    int row = blockIdx.x;
    const float* hr = h2 + (size_t)row * TC;
    int tid = threadIdx.x;

    float v[4];
    float a = 0.0f, q = 0.0f;
    #pragma unroll
    for (int i = 0; i < 4; i++) {
        int c = i * 256 + tid;
        v[i] = y1t[chunk32_pos(row, c, TM_TOTAL)] + hr[c];
        a += v[i];
        q += v[i] * v[i];
    }
    float2 r = blk_reduce_sum2(a, q, sbuf);
    float mean = r.x * (1.0f / (float)TC);
    float var  = r.y * (1.0f / (float)TC) - mean * mean;
    float rstd = rsqrtf(var + 1e-5f);
    #pragma unroll
    for (int i = 0; i < 4; i++) {
        int c = i * 256 + tid;
        out[(size_t)row * TC + c] = (v[i] - mean) * rstd * g[c] + be[c];
    }
}

// ===================== launcher =====================
extern "C" void kernel_launch(void* const* d_in, const int* in_sizes, int n_in,
                              void* d_out, int out_size)
{
    const float* x   = (const float*)d_in[0];
    const float* Wq  = (const float*)d_in[1];
    const float* bq  = (const float*)d_in[2];
    const float* Wk  = (const float*)d_in[3];
    const float* bk  = (const float*)d_in[4];
    const float* Wv  = (const float*)d_in[5];
    const float* bv  = (const float*)d_in[6];
    const float* g1  = (const float*)d_in[7];
    const float* be1 = (const float*)d_in[8];
    const float* W1  = (const float*)d_in[9];
    const float* bf1 = (const float*)d_in[10];
    const float* W2  = (const float*)d_in[11];
    const float* bf2 = (const float*)d_in[12];
    const float* g2  = (const float*)d_in[13];
    const float* be2 = (const float*)d_in[14];

    float *buf0, *buf1, *vsum, *wvs, *xt, *y1t, *h1t, *w32;
    float2* tw;
    cudaGetSymbolAddress((void**)&buf0, g_buf0);
    cudaGetSymbolAddress((void**)&buf1, g_buf1);
    cudaGetSymbolAddress((void**)&vsum, g_vsum);
    cudaGetSymbolAddress((void**)&wvs,  g_wvs);
    cudaGetSymbolAddress((void**)&tw,   g_tw);
    cudaGetSymbolAddress((void**)&xt,   g_xt);
    cudaGetSymbolAddress((void**)&y1t,  g_y1t);
    cudaGetSymbolAddress((void**)&h1t,  g_h1t);
    cudaGetSymbolAddress((void**)&w32,  g_w32);

    cudaFuncSetAttribute(gemm_tf32k<0>, cudaFuncAttributeMaxDynamicSharedMemorySize, GEMM32_SMEM);
    cudaFuncSetAttribute(gemm_tf32k<1>, cudaFuncAttributeMaxDynamicSharedMemorySize, GEMM32_SMEM);
    cudaFuncSetAttribute(gemm_tf32k<2>, cudaFuncAttributeMaxDynamicSharedMemorySize, GEMM32_SMEM);
    cudaFuncSetAttribute(trans_add_ln8, cudaFuncAttributeMaxDynamicSharedMemorySize, LN1_SMEM);

    const int M = TM_TOTAL;
    const size_t WSTRIDE = (size_t)TC * TC;
    dim3 wgrid(32, 32), wblk(32, 8);
    dim3 ggrid(TC / BN, M / BM);   // (8, 128)

    // prep (q-GEMM kept as 5th launch for ncu -s 5 -c 1)
    transpose_w32<<<wgrid, wblk>>>(Wq, w32 + 0*WSTRIDE);                          // 1
    transpose_w32<<<wgrid, wblk>>>(Wk, w32 + 1*WSTRIDE);                          // 2
    wvsum_kernel<<<TC + 1, 256>>>(Wv, bv, wvs);                                   // 3
    split_vsum_kernel<<<M, 256>>>(x, wvs, xt, vsum);                              // 4

    // q_t, k_t in [B,C,T] via tf32 GEMM with transposed epilogue
    gemm_tf32k<1><<<ggrid, 256, GEMM32_SMEM>>>(xt, w32 + 0*WSTRIDE, bq, buf0, nullptr);  // 5
    gemm_tf32k<1><<<ggrid, 256, GEMM32_SMEM>>>(xt, w32 + 1*WSTRIDE, bk, buf1, nullptr);  // 6

    // remaining prep
    init_tw_kernel<<<4, 256>>>(tw);
    transpose_w32<<<wgrid, wblk>>>(W1, w32 + 2*WSTRIDE);
    transpose_w32<<<wgrid, wblk>>>(W2, w32 + 3*WSTRIDE);

    // FFT xcorr + softmax + *vsum (channel-paired, radix-8 passes)
    fft_corr_softmax<<<TB * TC / 2, 256>>>(buf0, buf1, vsum, tw, buf0);

    // fused transpose + residual + LN1 -> tf32 chunk32
    trans_add_ln8<<<dim3(TT / TROWS, TB), 256, LN1_SMEM>>>(buf0, x, g1, be1, y1t);

    // FFN: tf32 single-pass GEMMs
    gemm_tf32k<2><<<ggrid, 256, GEMM32_SMEM>>>(y1t, w32 + 2*WSTRIDE, bf1, nullptr, h1t);
    gemm_tf32k<0><<<ggrid, 256, GEMM32_SMEM>>>(h1t, w32 + 3*WSTRIDE, bf2, buf1, nullptr);

    // LN2 (residual from y1t) -> out
    ln2_kernel<<<M, 256>>>(buf1, y1t, g2, be2, (float*)d_out);
}

// round 17
// speedup vs baseline: 1.2051x; 1.0339x over previous
#include <cuda_runtime.h>
#include <cuda_bf16.h>
#include <math_constants.h>
#include <cstdint>

// Problem shape (fixed by the dataset)
#define TB 8
#define TT 2048
#define TC 1024
#define TM_TOTAL (TB*TT)      // 16384 rows

// ===================== scratch (no allocations allowed) =====================
__device__ float g_buf0[TB * TC * TT];          // q_t [B,C,T] -> attn_t
__device__ float g_buf1[TB * TC * TT];          // k_t [B,C,T] -> h2 [B,T,C]
__device__ float g_vsum[TB * TT];
__device__ float g_wvs [TC + 1];
__device__ float2 g_tw [1024];                  // e^{-2pi i j/2048}

// tf32 operands, chunk-tiled fp32: [kc=32][row][32] (128B rows, SW128)
__device__ float g_xt [TM_TOTAL * TC];
__device__ float g_y1t[TM_TOTAL * TC];
__device__ float g_h1t[TM_TOTAL * TC];
__device__ float g_w32[4 * TC * TC];

// ===================== PTX helpers =====================
__device__ __forceinline__ uint32_t smem_u32(const void* p) {
    uint32_t a;
    asm("{ .reg .u64 t; cvta.to.shared.u64 t, %1; cvt.u32.u64 %0, t; }" : "=r"(a) : "l"(p));
    return a;
}
#define SMEM_SWIZZLE_128B(o) ((o) ^ (((o) >> 3) & 0x70))

#define MBARRIER_INIT(mb, cnt) \
    asm volatile("mbarrier.init.shared.b64 [%0], %1;" :: "r"((uint32_t)(mb)), "r"((uint32_t)(cnt)) : "memory")
#define MBARRIER_EXPECT_TX(mb, bytes) \
    asm volatile("mbarrier.arrive.expect_tx.shared.b64 _, [%0], %1;" :: "r"((uint32_t)(mb)), "r"((uint32_t)(bytes)) : "memory")
#define MBARRIER_WAIT_PARITY(mb, ph) do { \
    uint32_t _m = (uint32_t)(mb); uint32_t _p = (uint32_t)(ph); uint32_t _d; \
    asm volatile("{\n\t.reg .pred p;\n\tmbarrier.try_wait.parity.acquire.cta.shared::cta.b64 p, [%1], %2;\n\tselp.b32 %0, 1, 0, p;\n\t}" \
        : "=r"(_d) : "r"(_m), "r"(_p) : "memory"); \
    if (!_d) { \
        asm volatile("{\n\t.reg .pred P1;\n\tWL_%=:\n\tmbarrier.try_wait.parity.acquire.cta.shared::cta.b64 P1, [%0], %1, 0x989680;\n\t@P1 bra.uni WD_%=;\n\tbra.uni WL_%=;\n\tWD_%=:\n\t}" \
            :: "r"(_m), "r"(_p) : "memory"); \
    } } while (0)

#define BULK_G2S(dst, src, bytes, mbar) \
    asm volatile("cp.async.bulk.shared::cluster.global.mbarrier::complete_tx::bytes [%0], [%1], %2, [%3];" \
        :: "r"((uint32_t)(dst)), "l"(src), "r"((uint32_t)(bytes)), "r"((uint32_t)(mbar)) : "memory")

__device__ __forceinline__ void ldsm_x4(uint32_t* r, uint32_t addr) {
    asm volatile("ldmatrix.sync.aligned.m8n8.x4.shared.b16 {%0,%1,%2,%3}, [%4];"
                 : "=r"(r[0]), "=r"(r[1]), "=r"(r[2]), "=r"(r[3]) : "r"(addr));
}
__device__ __forceinline__ void ldsm_x2(uint32_t* r, uint32_t addr) {
    asm volatile("ldmatrix.sync.aligned.m8n8.x2.shared.b16 {%0,%1}, [%2];"
                 : "=r"(r[0]), "=r"(r[1]) : "r"(addr));
}
__device__ __forceinline__ void mma_tf32(float* d, const uint32_t* a, const uint32_t* b) {
    asm volatile("mma.sync.aligned.m16n8k8.row.col.f32.tf32.tf32.f32 "
                 "{%0,%1,%2,%3}, {%4,%5,%6,%7}, {%8,%9}, {%0,%1,%2,%3};"
                 : "+f"(d[0]), "+f"(d[1]), "+f"(d[2]), "+f"(d[3])
                 : "r"(a[0]), "r"(a[1]), "r"(a[2]), "r"(a[3]), "r"(b[0]), "r"(b[1]));
}
__device__ __forceinline__ float tf32r(float x) {
    uint32_t o;
    asm("cvt.rna.tf32.f32 %0, %1;" : "=r"(o) : "f"(x));
    return __uint_as_float(o);
}

// element index of (row r, col k) in fp32 chunked array (32 fp32/row) with R rows
__device__ __forceinline__ size_t chunk32_pos(int r, int k, int R) {
    uint32_t inb = SMEM_SWIZZLE_128B((uint32_t)((r & 127) * 128 + (k & 31) * 4));
    return (size_t)(k >> 5) * ((size_t)R * 32) + (size_t)(r & ~127) * 32 + (inb >> 2);
}

// ===================== block reductions (256 threads) =====================
__device__ __forceinline__ float blk_reduce_sum(float v, float* sbuf) {
    #pragma unroll
    for (int o = 16; o; o >>= 1) v += __shfl_xor_sync(0xffffffffu, v, o);
    if ((threadIdx.x & 31) == 0) sbuf[threadIdx.x >> 5] = v;
    __syncthreads();
    if (threadIdx.x < 32) {
        float w = (threadIdx.x < 8) ? sbuf[threadIdx.x] : 0.0f;
        #pragma unroll
        for (int o = 4; o; o >>= 1) w += __shfl_xor_sync(0xffffffffu, w, o);
        if (threadIdx.x == 0) sbuf[0] = w;
    }
    __syncthreads();
    float r = sbuf[0];
    __syncthreads();
    return r;
}
__device__ __forceinline__ float blk_reduce_max(float v, float* sbuf) {
    #pragma unroll
    for (int o = 16; o; o >>= 1) v = fmaxf(v, __shfl_xor_sync(0xffffffffu, v, o));
    if ((threadIdx.x & 31) == 0) sbuf[threadIdx.x >> 5] = v;
    __syncthreads();
    if (threadIdx.x < 32) {
        float w = (threadIdx.x < 8) ? sbuf[threadIdx.x] : -CUDART_INF_F;
        #pragma unroll
        for (int o = 4; o; o >>= 1) w = fmaxf(w, __shfl_xor_sync(0xffffffffu, w, o));
        if (threadIdx.x == 0) sbuf[0] = w;
    }
    __syncthreads();
    float r = sbuf[0];
    __syncthreads();
    return r;
}
__device__ __forceinline__ float2 blk_reduce_sum2(float a, float b, float* sbuf) {
    #pragma unroll
    for (int o = 16; o; o >>= 1) {
        a += __shfl_xor_sync(0xffffffffu, a, o);
        b += __shfl_xor_sync(0xffffffffu, b, o);
    }
    if ((threadIdx.x & 31) == 0) {
        sbuf[threadIdx.x >> 5] = a;
        sbuf[8 + (threadIdx.x >> 5)] = b;
    }
    __syncthreads();
    if (threadIdx.x < 32) {
        float wa = (threadIdx.x < 8) ? sbuf[threadIdx.x] : 0.0f;
        float wb = (threadIdx.x < 8) ? sbuf[8 + threadIdx.x] : 0.0f;
        #pragma unroll
        for (int o = 4; o; o >>= 1) {
            wa += __shfl_xor_sync(0xffffffffu, wa, o);
            wb += __shfl_xor_sync(0xffffffffu, wb, o);
        }
        if (threadIdx.x == 0) { sbuf[0] = wa; sbuf[1] = wb; }
    }
    __syncthreads();
    float2 r = make_float2(sbuf[0], sbuf[1]);
    __syncthreads();
    return r;
}

// ===================== tf32 single-pass GEMM (round-13 champion; FFN) =====================
// D[16384,1024] = A @ Wt^T + bias; A/Wt tf32-rounded fp32 in chunk32 layout.
// EPI: 0 = fp32 [M,N] + bias;  2 = relu + tf32 chunk32
#define BM 128
#define BN 128
#define NCH32 32
#define TSZ32 16384                     // 128 rows x 128B
#define ST32 (2*TSZ32)                  // 32KB
#define NST32 4
#define MB32_OFF (NST32*ST32)
#define GEMM32_SMEM (NST32*ST32 + 64)

__device__ __forceinline__ void gemm32_issue(const char* pA, const char* pB,
                                             int kc, uint32_t dst, uint32_t mb)
{
    MBARRIER_EXPECT_TX(mb, ST32);
    BULK_G2S(dst,         pA + (size_t)kc * ((size_t)TM_TOTAL * 128), TSZ32, mb);
    BULK_G2S(dst + TSZ32, pB + (size_t)kc * ((size_t)TC * 128),       TSZ32, mb);
}

template<int EPI>
__global__ void __launch_bounds__(256, 1)
gemm_tf32k(const float* __restrict__ A, const float* __restrict__ B,
           const float* __restrict__ bias, float* out_f, float* out_t)
{
    extern __shared__ char smem[];
    const uint32_t sb = smem_u32(smem);
    const int tid = threadIdx.x;
    const int wid = tid >> 5;
    const int lane = tid & 31;
    const int wm = wid & 1;
    const int wn = wid >> 1;
    const int n0 = blockIdx.x * BN;
    const int m0 = blockIdx.y * BM;

    const char* pA = (const char*)A + (size_t)m0 * 128;
    const char* pB = (const char*)B + (size_t)n0 * 128;

    if (tid == 0) {
        #pragma unroll
        for (int s = 0; s < NST32; s++) MBARRIER_INIT(sb + MB32_OFF + 8*s, 1);
    }
    __syncthreads();
    if (tid == 0) {
        #pragma unroll
        for (int s = 0; s < NST32; s++)
            gemm32_issue(pA, pB, s, sb + s*ST32, sb + MB32_OFF + 8*s);
    }

    float acc[4][4][4];
    #pragma unroll
    for (int mi = 0; mi < 4; mi++)
        #pragma unroll
        for (int ni = 0; ni < 4; ni++)
            #pragma unroll
            for (int e = 0; e < 4; e++) acc[mi][ni][e] = 0.0f;

    int ph[NST32] = {0, 0, 0, 0};
    int s = 0;
    #pragma unroll 1
    for (int kc = 0; kc < NCH32; kc++) {
        MBARRIER_WAIT_PARITY(sb + MB32_OFF + 8*s, ph[s]); ph[s] ^= 1;
        const uint32_t st = sb + s * ST32;
        #pragma unroll
        for (int ks = 0; ks < 4; ks++) {
            uint32_t af[4][4], bfr[4][2];
            const int arow = wm * 64 + ((lane >> 3) & 1) * 8 + (lane & 7);
            const int acolb = ks * 32 + (lane >> 4) * 16;
            #pragma unroll
            for (int mi = 0; mi < 4; mi++) {
                uint32_t o = SMEM_SWIZZLE_128B((uint32_t)((arow + mi*16) * 128 + acolb));
                ldsm_x4(af[mi], st + o);
            }
            const int brow = wn * 32 + (lane & 7);
            const int bcolb = ks * 32 + ((lane >> 3) & 1) * 16;
            #pragma unroll
            for (int ni = 0; ni < 4; ni++) {
                uint32_t o = SMEM_SWIZZLE_128B((uint32_t)((brow + ni*8) * 128 + bcolb));
                ldsm_x2(bfr[ni], st + TSZ32 + o);
            }
            #pragma unroll
            for (int mi = 0; mi < 4; mi++)
                #pragma unroll
                for (int ni = 0; ni < 4; ni++)
                    mma_tf32(acc[mi][ni], af[mi], bfr[ni]);
        }
        __syncthreads();
        if (kc + NST32 < NCH32 && tid == 0)
            gemm32_issue(pA, pB, kc + NST32, st, sb + MB32_OFF + 8*s);
        s = (s == NST32-1) ? 0 : s + 1;
    }

    float* stile = (float*)smem;
    {
        const int rg = lane >> 2;
        const int cg = (lane & 3) * 2;
        #pragma unroll
        for (int mi = 0; mi < 4; mi++)
            #pragma unroll
            for (int ni = 0; ni < 4; ni++) {
                int r = wm*64 + mi*16 + rg;
                int c = wn*32 + ni*8 + cg;
                stile[r*133 + c]         = acc[mi][ni][0];
                stile[r*133 + c + 1]     = acc[mi][ni][1];
                stile[(r+8)*133 + c]     = acc[mi][ni][2];
                stile[(r+8)*133 + c + 1] = acc[mi][ni][3];
            }
    }
    __syncthreads();

    if (EPI == 0) {
        for (int idx = tid; idx < BM*BN; idx += 256) {
            int r = idx >> 7, c = idx & 127;
            out_f[(size_t)(m0 + r) * TC + n0 + c] = stile[r*133 + c] + __ldg(bias + n0 + c);
        }
    } else {
        for (int idx = tid; idx < BM*BN; idx += 256) {
            int r = idx >> 7, c = idx & 127;
            float v = fmaxf(stile[r*133 + c] + __ldg(bias + n0 + c), 0.0f);
            out_t[chunk32_pos(m0 + r, n0 + c, TM_TOTAL)] = tf32r(v);
        }
    }
}

// ===================== fused Q+K GEMM (shared A operand) =====================
// q = A @ Wq^T + bq ; k = A @ Wk^T + bk ; both written transposed [B,C,T].
// Stage = [A | Bq | Bk] = 48KB, NST=3 (144KB smem).
#define QST (3*TSZ32)
#define QNST 3
#define QMB_OFF (QNST*QST)
#define GEMMQK_SMEM (QNST*QST + 64)

__device__ __forceinline__ void gemmqk_issue(const char* pA, const char* pBq, const char* pBk,
                                             int kc, uint32_t dst, uint32_t mb)
{
    MBARRIER_EXPECT_TX(mb, QST);
    BULK_G2S(dst,           pA  + (size_t)kc * ((size_t)TM_TOTAL * 128), TSZ32, mb);
    BULK_G2S(dst + TSZ32,   pBq + (size_t)kc * ((size_t)TC * 128),       TSZ32, mb);
    BULK_G2S(dst + 2*TSZ32, pBk + (size_t)kc * ((size_t)TC * 128),       TSZ32, mb);
}

__global__ void __launch_bounds__(256, 1)
gemm_qk(const float* __restrict__ A,
        const float* __restrict__ Bq, const float* __restrict__ Bk,
        const float* __restrict__ biasq, const float* __restrict__ biask,
        float* __restrict__ outq, float* __restrict__ outk)
{
    extern __shared__ char smem[];
    const uint32_t sb = smem_u32(smem);
    const int tid = threadIdx.x;
    const int wid = tid >> 5;
    const int lane = tid & 31;
    const int wm = wid & 1;
    const int wn = wid >> 1;
    const int n0 = blockIdx.x * BN;
    const int m0 = blockIdx.y * BM;

    const char* pA  = (const char*)A  + (size_t)m0 * 128;
    const char* pBq = (const char*)Bq + (size_t)n0 * 128;
    const char* pBk = (const char*)Bk + (size_t)n0 * 128;

    if (tid == 0) {
        #pragma unroll
        for (int s = 0; s < QNST; s++) MBARRIER_INIT(sb + QMB_OFF + 8*s, 1);
    }
    __syncthreads();
    if (tid == 0) {
        #pragma unroll
        for (int s = 0; s < QNST; s++)
            gemmqk_issue(pA, pBq, pBk, s, sb + s*QST, sb + QMB_OFF + 8*s);
    }

    float accq[4][4][4], acck[4][4][4];
    #pragma unroll
    for (int mi = 0; mi < 4; mi++)
        #pragma unroll
        for (int ni = 0; ni < 4; ni++)
            #pragma unroll
            for (int e = 0; e < 4; e++) { accq[mi][ni][e] = 0.0f; acck[mi][ni][e] = 0.0f; }

    int ph[QNST] = {0, 0, 0};
    int s = 0;
    #pragma unroll 1
    for (int kc = 0; kc < NCH32; kc++) {
        MBARRIER_WAIT_PARITY(sb + QMB_OFF + 8*s, ph[s]); ph[s] ^= 1;
        const uint32_t st = sb + s * QST;
        #pragma unroll
        for (int ks = 0; ks < 4; ks++) {
            uint32_t af[4][4], bq[4][2], bk[4][2];
            const int arow = wm * 64 + ((lane >> 3) & 1) * 8 + (lane & 7);
            const int acolb = ks * 32 + (lane >> 4) * 16;
            #pragma unroll
            for (int mi = 0; mi < 4; mi++) {
                uint32_t o = SMEM_SWIZZLE_128B((uint32_t)((arow + mi*16) * 128 + acolb));
                ldsm_x4(af[mi], st + o);
            }
            const int brow = wn * 32 + (lane & 7);
            const int bcolb = ks * 32 + ((lane >> 3) & 1) * 16;
            #pragma unroll
            for (int ni = 0; ni < 4; ni++) {
                uint32_t o = SMEM_SWIZZLE_128B((uint32_t)((brow + ni*8) * 128 + bcolb));
                ldsm_x2(bq[ni], st + TSZ32 + o);
                ldsm_x2(bk[ni], st + 2*TSZ32 + o);
            }
            #pragma unroll
            for (int mi = 0; mi < 4; mi++)
                #pragma unroll
                for (int ni = 0; ni < 4; ni++) {
                    mma_tf32(accq[mi][ni], af[mi], bq[ni]);
                    mma_tf32(acck[mi][ni], af[mi], bk[ni]);
                }
        }
        __syncthreads();
        if (kc + QNST < NCH32 && tid == 0)
            gemmqk_issue(pA, pBq, pBk, kc + QNST, st, sb + QMB_OFF + 8*s);
        s = (s == QNST-1) ? 0 : s + 1;
    }

    // epilogue: two stile passes (q then k), transposed [B,C,T] writes
    float* stile = (float*)smem;
    const int b = m0 >> 11, t0 = m0 & (TT - 1);
    const int rg = lane >> 2;
    const int cg = (lane & 3) * 2;

    #pragma unroll
    for (int mi = 0; mi < 4; mi++)
        #pragma unroll
        for (int ni = 0; ni < 4; ni++) {
            int r = wm*64 + mi*16 + rg;
            int c = wn*32 + ni*8 + cg;
            stile[r*133 + c]         = accq[mi][ni][0];
            stile[r*133 + c + 1]     = accq[mi][ni][1];
            stile[(r+8)*133 + c]     = accq[mi][ni][2];
            stile[(r+8)*133 + c + 1] = accq[mi][ni][3];
        }
    __syncthreads();
    for (int idx = tid; idx < BM*BN; idx += 256) {
        int n = idx >> 7, cm = idx & 127;
        float v = stile[cm*133 + n] + __ldg(biasq + n0 + n);
        outq[((size_t)(b * TC + n0 + n)) * TT + t0 + cm] = v;
    }
    __syncthreads();

    #pragma unroll
    for (int mi = 0; mi < 4; mi++)
        #pragma unroll
        for (int ni = 0; ni < 4; ni++) {
            int r = wm*64 + mi*16 + rg;
            int c = wn*32 + ni*8 + cg;
            stile[r*133 + c]         = acck[mi][ni][0];
            stile[r*133 + c + 1]     = acck[mi][ni][1];
            stile[(r+8)*133 + c]     = acck[mi][ni][2];
            stile[(r+8)*133 + c + 1] = acck[mi][ni][3];
        }
    __syncthreads();
    for (int idx = tid; idx < BM*BN; idx += 256) {
        int n = idx >> 7, cm = idx & 127;
        float v = stile[cm*133 + n] + __ldg(biask + n0 + n);
        outk[((size_t)(b * TC + n0 + n)) * TT + t0 + cm] = v;
    }
}

// ===================== fused: fp32 x -> tf32 chunk32 + vsum GEMV =====================
__global__ void __launch_bounds__(256)
split_vsum_kernel(const float* __restrict__ x, const float* __restrict__ wvs,
                  float* __restrict__ xt, float* __restrict__ vsum)
{
    __shared__ float sbuf[32];
    const int m = blockIdx.x;
    const int tid = threadIdx.x;
    const float* xr = x + (size_t)m * TC;

    const int c = tid * 4;
    float4 v = *(const float4*)(xr + c);
    float s = v.x * __ldg(wvs + c) + v.y * __ldg(wvs + c + 1)
            + v.z * __ldg(wvs + c + 2) + v.w * __ldg(wvs + c + 3);

    float4 t;
    t.x = tf32r(v.x); t.y = tf32r(v.y); t.z = tf32r(v.z); t.w = tf32r(v.w);
    *(float4*)(xt + chunk32_pos(m, c, TM_TOTAL)) = t;

    s = blk_reduce_sum(s, sbuf);
    if (tid == 0) vsum[m] = s + __ldg(wvs + TC);
}

// ===================== W[K,N] -> Wt[N,K] tf32 chunk32 =====================
__global__ void transpose_w32(const float* __restrict__ W, float* __restrict__ out)
{
    __shared__ float tile[32][33];
    const int n0 = blockIdx.x * 32;
    const int k0 = blockIdx.y * 32;
    #pragma unroll
    for (int y = threadIdx.y; y < 32; y += 8)
        tile[y][threadIdx.x] = W[(size_t)(k0 + y) * TC + n0 + threadIdx.x];
    __syncthreads();
    #pragma unroll
    for (int y = threadIdx.y; y < 32; y += 8)
        out[chunk32_pos(n0 + y, k0 + threadIdx.x, TC)] = tf32r(tile[threadIdx.x][y]);
}

// ===================== wvsum / twiddles =====================
__global__ void wvsum_kernel(const float* __restrict__ Wv, const float* __restrict__ bv,
                             float* __restrict__ out)
{
    __shared__ float sbuf[32];
    int d = blockIdx.x;
    const float* src = (d < TC) ? (Wv + (size_t)d * TC) : bv;
    float s = 0.0f;
    for (int c = threadIdx.x; c < TC; c += 256) s += src[c];
    s = blk_reduce_sum(s, sbuf);
    if (threadIdx.x == 0) out[d] = s;
}
__global__ void init_tw_kernel(float2* __restrict__ tw)
{
    int j = blockIdx.x * 256 + threadIdx.x;
    float sv, cv;
    sincosf(-6.283185307179586f * ((float)j * (1.0f / 2048.0f)), &sv, &cv);
    tw[j] = make_float2(cv, sv);
}

// ===================== FFT machinery =====================
__device__ __forceinline__ float2 cmulf(float2 a, float2 b) {
    return make_float2(a.x*b.x - a.y*b.y, a.x*b.y + a.y*b.x);
}
#define BFLY(u, v, w) do { \
    float2 _t = cmulf(v, w); \
    v = make_float2(u.x - _t.x, u.y - _t.y); \
    u = make_float2(u.x + _t.x, u.y + _t.y); \
} while (0)

template<int H>
__device__ __forceinline__ void fft_r4_pass(float2* z, const float2* tw, int tid, bool inv)
{
    #pragma unroll
    for (int jj = 0; jj < 2; jj++) {
        int j = tid + jj * 256;
        int grp = j / H;
        int p = j & (H - 1);
        int i0 = grp * 4 * H + p;
        float2 w1 = tw[p * (1024 / H)];
        float2 w2 = tw[p * (512 / H)];
        if (inv) { w1.y = -w1.y; w2.y = -w2.y; }
        float2 w2b = inv ? make_float2(-w2.y, w2.x) : make_float2(w2.y, -w2.x);
        float2 e0 = z[i0], e1 = z[i0+H], e2 = z[i0+2*H], e3 = z[i0+3*H];
        BFLY(e0, e1, w1);
        BFLY(e2, e3, w1);
        BFLY(e0, e2, w2);
        BFLY(e1, e3, w2b);
        z[i0] = e0; z[i0+H] = e1; z[i0+2*H] = e2; z[i0+3*H] = e3;
    }
}

template<int H>
__device__ __forceinline__ void fft_r8_pass(float2* z, const float2* tw, int tid, bool inv)
{
    const int g = tid / H;
    const int p = tid % H;
    const int i0 = g * 8 * H + p;
    float2 w1 = tw[p * (1024 / H)];
    float2 w2 = tw[p * (512 / H)];
    float2 w3 = tw[p * (256 / H)];
    if (inv) { w1.y = -w1.y; w2.y = -w2.y; w3.y = -w3.y; }
    const float R = 0.70710678118654752440f;
    const float2 c8 = inv ? make_float2(R, R) : make_float2(R, -R);
    float2 w2b  = inv ? make_float2(-w2.y, w2.x)   : make_float2(w2.y, -w2.x);
    float2 w3_1 = cmulf(w3, c8);
    float2 w3_2 = inv ? make_float2(-w3.y, w3.x)   : make_float2(w3.y, -w3.x);
    float2 w3_3 = inv ? make_float2(-w3_1.y, w3_1.x) : make_float2(w3_1.y, -w3_1.x);

    float2 e0 = z[i0],       e1 = z[i0+H],   e2 = z[i0+2*H], e3 = z[i0+3*H];
    float2 e4 = z[i0+4*H],   e5 = z[i0+5*H], e6 = z[i0+6*H], e7 = z[i0+7*H];
    BFLY(e0, e1, w1); BFLY(e2, e3, w1); BFLY(e4, e5, w1); BFLY(e6, e7, w1);
    BFLY(e0, e2, w2); BFLY(e1, e3, w2b); BFLY(e4, e6, w2); BFLY(e5, e7, w2b);
    BFLY(e0, e4, w3); BFLY(e1, e5, w3_1); BFLY(e2, e6, w3_2); BFLY(e3, e7, w3_3);
    z[i0] = e0;       z[i0+H] = e1;   z[i0+2*H] = e2; z[i0+3*H] = e3;
    z[i0+4*H] = e4;   z[i0+5*H] = e5; z[i0+6*H] = e6; z[i0+7*H] = e7;
}

template<bool DUAL>
__device__ __forceinline__ void fft_seq(float2* za, float2* zb, const float2* tw, int tid, bool inv)
{
    fft_r4_pass<1>(za, tw, tid, inv);
    if (DUAL) fft_r4_pass<1>(zb, tw, tid, inv);
    __syncthreads();
    fft_r8_pass<4>(za, tw, tid, inv);
    if (DUAL) fft_r8_pass<4>(zb, tw, tid, inv);
    __syncthreads();
    fft_r8_pass<32>(za, tw, tid, inv);
    if (DUAL) fft_r8_pass<32>(zb, tw, tid, inv);
    __syncthreads();
    fft_r8_pass<256>(za, tw, tid, inv);
    if (DUAL) fft_r8_pass<256>(zb, tw, tid, inv);
    __syncthreads();
}

__global__ void __launch_bounds__(256)
fft_corr_softmax(const float* qt, const float* kt,
                 const float* __restrict__ vsum, const float2* __restrict__ gtw,
                 float* attn_t)
{
    __shared__ float2 zq[2048];
    __shared__ float2 zk[2048];
    __shared__ float2 tw[1024];
    __shared__ float sbuf[32];

    const int pc = blockIdx.x;
    const int b = pc >> 9;
    const int c0 = (pc & 511) * 2;
    const int tid = threadIdx.x;
    const float* q0 = qt + ((size_t)b * TC + c0) * TT;
    const float* q1 = q0 + TT;
    const float* k0 = kt + ((size_t)b * TC + c0) * TT;
    const float* k1 = k0 + TT;

    #pragma unroll
    for (int i = 0; i < 2; i++) {
        int j = tid + i * 256;
        ((float4*)tw)[j] = __ldg((const float4*)gtw + j);
    }
    #pragma unroll
    for (int i = 0; i < 8; i++) {
        int t = tid + i * 256;
        int r = __brev((unsigned)t) >> 21;
        zq[r] = make_float2(q0[t], q1[t]);
        zk[r] = make_float2(k0[t], k1[t]);
    }
    __syncthreads();

    fft_seq<true>(zq, zk, tw, tid, false);

    for (int f = tid; f <= 1024; f += 256) {
        int g = (2048 - f) & 2047;
        float2 aq = zq[f], bq = zq[g];
        float2 ak = zk[f], bk = zk[g];
        float Q0r = 0.5f*(aq.x + bq.x), Q0i = 0.5f*(aq.y - bq.y);
        float Q1r = 0.5f*(aq.y + bq.y), Q1i = 0.5f*(bq.x - aq.x);
        float K0r = 0.5f*(ak.x + bk.x), K0i = 0.5f*(ak.y - bk.y);
        float K1r = 0.5f*(ak.y + bk.y), K1i = 0.5f*(bk.x - ak.x);
        float P0r = Q0r*K0r + Q0i*K0i, P0i = Q0i*K0r - Q0r*K0i;
        float P1r = Q1r*K1r + Q1i*K1i, P1i = Q1i*K1r - Q1r*K1i;
        zq[f] = make_float2(P0r - P1i, P0i + P1r);
        zq[g] = make_float2(P0r + P1i, P1r - P0i);
    }
    __syncthreads();

    #pragma unroll
    for (int i = 0; i < 8; i++) {
        int t = tid + i * 256;
        int r = __brev((unsigned)t) >> 21;
        if (r > t) { float2 a = zq[t]; zq[t] = zq[r]; zq[r] = a; }
    }
    __syncthreads();
    fft_seq<false>(zq, nullptr, tw, tid, true);

    float c0v[8], c1v[8];
    float m0 = -CUDART_INF_F, m1 = -CUDART_INF_F;
    #pragma unroll
    for (int i = 0; i < 8; i++) {
        int t = tid + i * 256;
        float2 w = zq[t];
        c0v[i] = w.x * (1.0f / 2048.0f);
        c1v[i] = w.y * (1.0f / 2048.0f);
        m0 = fmaxf(m0, c0v[i]);
        m1 = fmaxf(m1, c1v[i]);
    }
    m0 = blk_reduce_max(m0, sbuf);
    m1 = blk_reduce_max(m1, sbuf);
    float s0 = 0.0f, s1 = 0.0f;
    #pragma unroll
    for (int i = 0; i < 8; i++) {
        c0v[i] = expf(c0v[i] - m0);
        c1v[i] = expf(c1v[i] - m1);
        s0 += c0v[i];
        s1 += c1v[i];
    }
    s0 = blk_reduce_sum(s0, sbuf);
    s1 = blk_reduce_sum(s1, sbuf);
    float i0 = 1.0f / s0, i1 = 1.0f / s1;

    const float* vs = vsum + (size_t)b * TT;
    float* a0 = attn_t + ((size_t)b * TC + c0) * TT;
    float* a1 = a0 + TT;
    #pragma unroll
    for (int i = 0; i < 8; i++) {
        int t = tid + i * 256;
        float v = vs[t];
        a0[t] = c0v[i] * i0 * v;
        a1[t] = c1v[i] * i1 * v;
    }
}

// ===================== fused: transpose + residual + LN1 -> tf32 chunk32 =====================
#define TROWS 8
#define TPAD 1025
#define LN1_SMEM (TROWS * TPAD * 4)

__global__ void __launch_bounds__(256)
trans_add_ln8(const float* __restrict__ attn_t, const float* __restrict__ x,
              const float* __restrict__ g, const float* __restrict__ be,
              float* __restrict__ y1t)
{
    extern __shared__ float s[];
    __shared__ float sbuf[64];
    const int b  = blockIdx.y;
    const int t0 = blockIdx.x * TROWS;
    const int tid = threadIdx.x;

    #pragma unroll
    for (int i = 0; i < 32; i++) {
        int idx = tid + i * 256;
        int c = idx >> 3, j = idx & 7;
        s[j * TPAD + c] = attn_t[((size_t)b * TC + c) * TT + t0 + j];
    }
    __syncthreads();
    #pragma unroll
    for (int i = 0; i < 32; i++) {
        int idx = tid + i * 256;
        int j = idx >> 10, c = idx & 1023;
        s[j * TPAD + c] += x[((size_t)b * TT + t0 + j) * TC + c];
    }
    __syncthreads();

    #pragma unroll 1
    for (int j = 0; j < TROWS; j++) {
        const int row = b * TT + t0 + j;
        const float* srow = s + j * TPAD;
        float a = 0.0f, q = 0.0f;
        float v[4];
        #pragma unroll
        for (int i = 0; i < 4; i++) {
            v[i] = srow[i * 256 + tid];
            a += v[i];
            q += v[i] * v[i];
        }
        float2 r = blk_reduce_sum2(a, q, sbuf);
        float mean = r.x * (1.0f / (float)TC);
        float var  = r.y * (1.0f / (float)TC) - mean * mean;
        float rstd = rsqrtf(var + 1e-5f);
        #pragma unroll
        for (int i = 0; i < 4; i++) {
            int c = i * 256 + tid;
            float y = (v[i] - mean) * rstd * __ldg(g + c) + __ldg(be + c);
            y1t[chunk32_pos(row, c, TM_TOTAL)] = tf32r(y);
        }
    }
}

// ===================== LN2: residual from y1t + h2 fp32 -> final out =====================
__global__ void __launch_bounds__(256)
ln2_kernel(const float* __restrict__ h2, const float* __restrict__ y1t,
           const float* __restrict__ g, const float* __restrict__ be,
           float* __restrict__ out)
{
    __shared__ float sbuf[64];
    int row = blockIdx.x;
    const float* hr = h2 + (size_t)row * TC;
    int tid = threadIdx.x;

    float v[4];
    float a = 0.0f, q = 0.0f;
    #pragma unroll
    for (int i = 0; i < 4; i++) {
        int c = i * 256 + tid;
        v[i] = y1t[chunk32_pos(row, c, TM_TOTAL)] + hr[c];
        a += v[i];
        q += v[i] * v[i];
    }
    float2 r = blk_reduce_sum2(a, q, sbuf);
    float mean = r.x * (1.0f / (float)TC);
    float var  = r.y * (1.0f / (float)TC) - mean * mean;
    float rstd = rsqrtf(var + 1e-5f);
    #pragma unroll
    for (int i = 0; i < 4; i++) {
        int c = i * 256 + tid;
        out[(size_t)row * TC + c] = (v[i] - mean) * rstd * g[c] + be[c];
    }
}

// ===================== launcher =====================
extern "C" void kernel_launch(void* const* d_in, const int* in_sizes, int n_in,
                              void* d_out, int out_size)
{
    const float* x   = (const float*)d_in[0];
    const float* Wq  = (const float*)d_in[1];
    const float* bq  = (const float*)d_in[2];
    const float* Wk  = (const float*)d_in[3];
    const float* bk  = (const float*)d_in[4];
    const float* Wv  = (const float*)d_in[5];
    const float* bv  = (const float*)d_in[6];
    const float* g1  = (const float*)d_in[7];
    const float* be1 = (const float*)d_in[8];
    const float* W1  = (const float*)d_in[9];
    const float* bf1 = (const float*)d_in[10];
    const float* W2  = (const float*)d_in[11];
    const float* bf2 = (const float*)d_in[12];
    const float* g2  = (const float*)d_in[13];
    const float* be2 = (const float*)d_in[14];

    float *buf0, *buf1, *vsum, *wvs, *xt, *y1t, *h1t, *w32;
    float2* tw;
    cudaGetSymbolAddress((void**)&buf0, g_buf0);
    cudaGetSymbolAddress((void**)&buf1, g_buf1);
    cudaGetSymbolAddress((void**)&vsum, g_vsum);
    cudaGetSymbolAddress((void**)&wvs,  g_wvs);
    cudaGetSymbolAddress((void**)&tw,   g_tw);
    cudaGetSymbolAddress((void**)&xt,   g_xt);
    cudaGetSymbolAddress((void**)&y1t,  g_y1t);
    cudaGetSymbolAddress((void**)&h1t,  g_h1t);
    cudaGetSymbolAddress((void**)&w32,  g_w32);

    cudaFuncSetAttribute(gemm_tf32k<0>, cudaFuncAttributeMaxDynamicSharedMemorySize, GEMM32_SMEM);
    cudaFuncSetAttribute(gemm_tf32k<2>, cudaFuncAttributeMaxDynamicSharedMemorySize, GEMM32_SMEM);
    cudaFuncSetAttribute(gemm_qk, cudaFuncAttributeMaxDynamicSharedMemorySize, GEMMQK_SMEM);
    cudaFuncSetAttribute(trans_add_ln8, cudaFuncAttributeMaxDynamicSharedMemorySize, LN1_SMEM);

    const int M = TM_TOTAL;
    const size_t WSTRIDE = (size_t)TC * TC;
    dim3 wgrid(32, 32), wblk(32, 8);
    dim3 ggrid(TC / BN, M / BM);   // (8, 128)

    // prep (fused QK-GEMM kept as 5th launch for ncu -s 5 -c 1)
    transpose_w32<<<wgrid, wblk>>>(Wq, w32 + 0*WSTRIDE);                          // 1
    transpose_w32<<<wgrid, wblk>>>(Wk, w32 + 1*WSTRIDE);                          // 2
    wvsum_kernel<<<TC + 1, 256>>>(Wv, bv, wvs);                                   // 3
    split_vsum_kernel<<<M, 256>>>(x, wvs, xt, vsum);                              // 4

    // fused q+k GEMM (shared A) with transposed epilogues
    gemm_qk<<<ggrid, 256, GEMMQK_SMEM>>>(xt, w32 + 0*WSTRIDE, w32 + 1*WSTRIDE,
                                         bq, bk, buf0, buf1);                     // 5

    // remaining prep
    init_tw_kernel<<<4, 256>>>(tw);
    transpose_w32<<<wgrid, wblk>>>(W1, w32 + 2*WSTRIDE);
    transpose_w32<<<wgrid, wblk>>>(W2, w32 + 3*WSTRIDE);

    // FFT xcorr + softmax + *vsum (channel-paired, radix-8 passes)
    fft_corr_softmax<<<TB * TC / 2, 256>>>(buf0, buf1, vsum, tw, buf0);

    // fused transpose + residual + LN1 -> tf32 chunk32
    trans_add_ln8<<<dim3(TT / TROWS, TB), 256, LN1_SMEM>>>(buf0, x, g1, be1, y1t);

    // FFN: tf32 single-pass GEMMs
    gemm_tf32k<2><<<ggrid, 256, GEMM32_SMEM>>>(y1t, w32 + 2*WSTRIDE, bf1, nullptr, h1t);
    gemm_tf32k<0><<<ggrid, 256, GEMM32_SMEM>>>(h1t, w32 + 3*WSTRIDE, bf2, buf1, nullptr);

    // LN2 (residual from y1t) -> out
    ln2_kernel<<<M, 256>>>(buf1, y1t, g2, be2, (float*)d_out);
}